// round 1
// baseline (speedup 1.0000x reference)
#include <cuda_runtime.h>
#include <math.h>

#define B_SZ   4
#define NLEN   4128
#define DIMN   1024
#define HEADS  16
#define BLKLEN 129
#define NB     32
#define DK     64
#define DV     64
#define TOK    (B_SZ * NLEN)   // 16512

// Scratch (device globals: allocation-free)
__device__ float g_q[TOK * DIMN];
__device__ float g_k[TOK * DIMN];
__device__ float g_v[TOK * DIMN];
__device__ float g_attn[TOK * DIMN];

// ---------------------------------------------------------------------------
// SGEMM: C[M,N] = A[M,K] @ B[N,K]^T (+bias). M%128==0, N%128==0, K%8==0.
// 128x128 block tile, BK=8, 8x8 per-thread microtile, 256 threads.
// ---------------------------------------------------------------------------
__global__ __launch_bounds__(256, 4)
void sgemm_tn(const float* __restrict__ A, const float* __restrict__ Bm,
              const float* __restrict__ bias, float* __restrict__ C,
              int M, int N, int K)
{
    __shared__ float As[8][128];
    __shared__ float Bs[8][128];

    const int m0 = blockIdx.y * 128;
    const int n0 = blockIdx.x * 128;
    const int tid = threadIdx.x;
    const int tr = tid >> 4;          // 0..15
    const int tc = tid & 15;          // 0..15
    const int lr = tid >> 1;          // 0..127 (load row)
    const int lc = (tid & 1) * 4;     // 0 or 4 (load col, float4)

    const float* Aptr = A + (size_t)(m0 + lr) * K + lc;
    const float* Bptr = Bm + (size_t)(n0 + lr) * K + lc;

    float acc[8][8];
#pragma unroll
    for (int i = 0; i < 8; i++)
#pragma unroll
        for (int j = 0; j < 8; j++) acc[i][j] = 0.f;

    for (int k0 = 0; k0 < K; k0 += 8) {
        float4 a4 = *(const float4*)(Aptr + k0);
        float4 b4 = *(const float4*)(Bptr + k0);
        __syncthreads();
        As[lc + 0][lr] = a4.x; As[lc + 1][lr] = a4.y;
        As[lc + 2][lr] = a4.z; As[lc + 3][lr] = a4.w;
        Bs[lc + 0][lr] = b4.x; Bs[lc + 1][lr] = b4.y;
        Bs[lc + 2][lr] = b4.z; Bs[lc + 3][lr] = b4.w;
        __syncthreads();

#pragma unroll
        for (int kk = 0; kk < 8; kk++) {
            float4 ra0 = *(const float4*)&As[kk][tr * 8];
            float4 ra1 = *(const float4*)&As[kk][tr * 8 + 4];
            float4 rb0 = *(const float4*)&Bs[kk][tc * 8];
            float4 rb1 = *(const float4*)&Bs[kk][tc * 8 + 4];
            float ra[8] = {ra0.x, ra0.y, ra0.z, ra0.w, ra1.x, ra1.y, ra1.z, ra1.w};
            float rb[8] = {rb0.x, rb0.y, rb0.z, rb0.w, rb1.x, rb1.y, rb1.z, rb1.w};
#pragma unroll
            for (int i = 0; i < 8; i++)
#pragma unroll
                for (int j = 0; j < 8; j++)
                    acc[i][j] += ra[i] * rb[j];
        }
    }

#pragma unroll
    for (int i = 0; i < 8; i++) {
        const int row = m0 + tr * 8 + i;
        float* cp = C + (size_t)row * N + n0 + tc * 8;
        float4 o0, o1;
        float b0 = 0.f, b1 = 0.f, b2 = 0.f, b3 = 0.f, b4 = 0.f, b5 = 0.f, b6 = 0.f, b7 = 0.f;
        if (bias) {
            const float* bp = bias + n0 + tc * 8;
            b0 = bp[0]; b1 = bp[1]; b2 = bp[2]; b3 = bp[3];
            b4 = bp[4]; b5 = bp[5]; b6 = bp[6]; b7 = bp[7];
        }
        o0.x = acc[i][0] + b0; o0.y = acc[i][1] + b1;
        o0.z = acc[i][2] + b2; o0.w = acc[i][3] + b3;
        o1.x = acc[i][4] + b4; o1.y = acc[i][5] + b5;
        o1.z = acc[i][6] + b6; o1.w = acc[i][7] + b7;
        *(float4*)cp = o0;
        *(float4*)(cp + 4) = o1;
    }
}

// ---------------------------------------------------------------------------
// Block-local attention: one block per (b, blk, head).
// K/V tile (129x64 each) in dynamic smem; q row + accumulator in registers.
// Softmax without max-subtraction (scores ~ N(0,1), fp32-safe).
// ---------------------------------------------------------------------------
#define ATTN_SMEM (2 * BLKLEN * DK * (int)sizeof(float))   // 66048 bytes

__global__ __launch_bounds__(160, 2)
void blk_attn(const float* __restrict__ Q, const float* __restrict__ Kt,
              const float* __restrict__ Vt, float* __restrict__ O)
{
    extern __shared__ float sm[];
    float* ks = sm;
    float* vs = sm + BLKLEN * DK;

    const int bid = blockIdx.x;                // 0..2047
    const int h   = bid & 15;
    const int blk = (bid >> 4) & 31;
    const int b   = bid >> 9;
    const size_t base = ((size_t)b * NLEN + (size_t)blk * BLKLEN) * DIMN + h * DK;
    const int tid = threadIdx.x;

    // cooperative load of K,V tiles (129 rows x 16 float4)
    for (int i = tid; i < BLKLEN * 16; i += 160) {
        const int r = i >> 4, c = i & 15;
        ((float4*)ks)[i] = *(const float4*)(Kt + base + (size_t)r * DIMN + c * 4);
        ((float4*)vs)[i] = *(const float4*)(Vt + base + (size_t)r * DIMN + c * 4);
    }
    __syncthreads();

    if (tid < BLKLEN) {
        float qr[64];
        const float4* qp = (const float4*)(Q + base + (size_t)tid * DIMN);
#pragma unroll
        for (int i = 0; i < 16; i++) {
            float4 t = qp[i];
            qr[4 * i + 0] = t.x; qr[4 * i + 1] = t.y;
            qr[4 * i + 2] = t.z; qr[4 * i + 3] = t.w;
        }
        float acc[64];
#pragma unroll
        for (int d = 0; d < 64; d++) acc[d] = 0.f;
        float l = 0.f;
        const float scale = 0.125f;   // 1/sqrt(64)

        for (int key = 0; key < BLKLEN; key++) {
            const float4* kp = (const float4*)(ks + key * DK);
            float s0 = 0.f, s1 = 0.f, s2 = 0.f, s3 = 0.f;
#pragma unroll
            for (int i = 0; i < 16; i++) {
                float4 kv = kp[i];
                s0 += qr[4 * i + 0] * kv.x;
                s1 += qr[4 * i + 1] * kv.y;
                s2 += qr[4 * i + 2] * kv.z;
                s3 += qr[4 * i + 3] * kv.w;
            }
            const float p = __expf(((s0 + s1) + (s2 + s3)) * scale);
            l += p;
            const float4* vp = (const float4*)(vs + key * DK);
#pragma unroll
            for (int i = 0; i < 16; i++) {
                float4 vv = vp[i];
                acc[4 * i + 0] += p * vv.x;
                acc[4 * i + 1] += p * vv.y;
                acc[4 * i + 2] += p * vv.z;
                acc[4 * i + 3] += p * vv.w;
            }
        }

        const float rl = 1.0f / l;
        float4* op = (float4*)(O + base + (size_t)tid * DIMN);
#pragma unroll
        for (int i = 0; i < 16; i++) {
            float4 t;
            t.x = acc[4 * i + 0] * rl; t.y = acc[4 * i + 1] * rl;
            t.z = acc[4 * i + 2] * rl; t.w = acc[4 * i + 3] * rl;
            op[i] = t;
        }
    }
}

// ---------------------------------------------------------------------------
// Global attention over the first token of each block: one CTA per (b,h),
// 32 queries x 32 keys, accumulated (+=) into g_attn.
// ---------------------------------------------------------------------------
__global__ __launch_bounds__(32)
void glob_attn(const float* __restrict__ Q, const float* __restrict__ Kt,
               const float* __restrict__ Vt, float* __restrict__ O)
{
    __shared__ float ks[NB * DK];
    __shared__ float vs[NB * DK];
    const int b = blockIdx.x >> 4;
    const int h = blockIdx.x & 15;
    const int tid = threadIdx.x;   // 0..31  (= global query / key index)

    const size_t rowbase = ((size_t)b * NLEN + (size_t)tid * BLKLEN) * DIMN + h * DK;
    // each thread loads its own key/value row (token = first of block tid)
#pragma unroll
    for (int i = 0; i < 16; i++) {
        ((float4*)(ks + tid * DK))[i] = *(const float4*)(Kt + rowbase + i * 4);
        ((float4*)(vs + tid * DK))[i] = *(const float4*)(Vt + rowbase + i * 4);
    }
    __syncthreads();

    float qr[64];
    const float4* qp = (const float4*)(Q + rowbase);
#pragma unroll
    for (int i = 0; i < 16; i++) {
        float4 t = qp[i];
        qr[4 * i + 0] = t.x; qr[4 * i + 1] = t.y;
        qr[4 * i + 2] = t.z; qr[4 * i + 3] = t.w;
    }
    float acc[64];
#pragma unroll
    for (int d = 0; d < 64; d++) acc[d] = 0.f;
    float l = 0.f;
    const float scale = 0.125f;

    for (int key = 0; key < NB; key++) {
        const float4* kp = (const float4*)(ks + key * DK);
        float s0 = 0.f, s1 = 0.f, s2 = 0.f, s3 = 0.f;
#pragma unroll
        for (int i = 0; i < 16; i++) {
            float4 kv = kp[i];
            s0 += qr[4 * i + 0] * kv.x;
            s1 += qr[4 * i + 1] * kv.y;
            s2 += qr[4 * i + 2] * kv.z;
            s3 += qr[4 * i + 3] * kv.w;
        }
        const float p = __expf(((s0 + s1) + (s2 + s3)) * scale);
        l += p;
        const float4* vp = (const float4*)(vs + key * DK);
#pragma unroll
        for (int i = 0; i < 16; i++) {
            float4 vv = vp[i];
            acc[4 * i + 0] += p * vv.x;
            acc[4 * i + 1] += p * vv.y;
            acc[4 * i + 2] += p * vv.z;
            acc[4 * i + 3] += p * vv.w;
        }
    }

    const float rl = 1.0f / l;
    float4* op = (float4*)(O + rowbase);
#pragma unroll
    for (int i = 0; i < 16; i++) {
        float4 t = op[i];
        t.x += acc[4 * i + 0] * rl; t.y += acc[4 * i + 1] * rl;
        t.z += acc[4 * i + 2] * rl; t.w += acc[4 * i + 3] * rl;
        op[i] = t;
    }
}

// ---------------------------------------------------------------------------
extern "C" void kernel_launch(void* const* d_in, const int* in_sizes, int n_in,
                              void* d_out, int out_size)
{
    const float* x  = (const float*)d_in[0];
    const float* Wq = (const float*)d_in[1];
    const float* Wk = (const float*)d_in[2];
    const float* Wv = (const float*)d_in[3];
    const float* Wo = (const float*)d_in[4];
    const float* bo = (const float*)d_in[5];
    float* out = (float*)d_out;

    float *q, *k, *v, *attn;
    cudaGetSymbolAddress((void**)&q,    g_q);
    cudaGetSymbolAddress((void**)&k,    g_k);
    cudaGetSymbolAddress((void**)&v,    g_v);
    cudaGetSymbolAddress((void**)&attn, g_attn);

    cudaFuncSetAttribute(blk_attn, cudaFuncAttributeMaxDynamicSharedMemorySize,
                         ATTN_SMEM);

    dim3 gProj(DIMN / 128, TOK / 128);   // (8, 129)

    sgemm_tn<<<gProj, 256>>>(x, Wq, nullptr, q, TOK, DIMN, DIMN);
    sgemm_tn<<<gProj, 256>>>(x, Wk, nullptr, k, TOK, DIMN, DIMN);
    sgemm_tn<<<gProj, 256>>>(x, Wv, nullptr, v, TOK, DIMN, DIMN);

    blk_attn<<<B_SZ * NB * HEADS, 160, ATTN_SMEM>>>(q, k, v, attn);
    glob_attn<<<B_SZ * HEADS, 32>>>(q, k, v, attn);

    sgemm_tn<<<gProj, 256>>>(attn, Wo, bo, out, TOK, DIMN, DIMN);
}

// round 2
// speedup vs baseline: 8.3620x; 8.3620x over previous
#include <cuda_runtime.h>
#include <cuda_bf16.h>
#include <cstdint>
#include <math.h>

#define B_SZ   4
#define NLEN   4128
#define DIMN   1024
#define HEADS  16
#define BLKLEN 129
#define NB     32
#define DK     64
#define TOK    (B_SZ * NLEN)   // 16512

// ---------------- scratch (device globals: allocation-free) ----------------
__device__ float g_q[TOK * DIMN];
__device__ float g_k[TOK * DIMN];
__device__ float g_v[TOK * DIMN];
__device__ float g_attn[TOK * DIMN];
__device__ __nv_bfloat16 g_xhi[TOK * DIMN];
__device__ __nv_bfloat16 g_xlo[TOK * DIMN];
__device__ __nv_bfloat16 g_ahi[TOK * DIMN];
__device__ __nv_bfloat16 g_alo[TOK * DIMN];
__device__ __nv_bfloat16 g_whi[4 * DIMN * DIMN];
__device__ __nv_bfloat16 g_wlo[4 * DIMN * DIMN];

// ---------------------------------------------------------------------------
// fp32 -> (hi, lo) bf16 split, vectorized x4
// ---------------------------------------------------------------------------
__global__ void cvt_split4(const float4* __restrict__ in,
                           __nv_bfloat162* __restrict__ hi,
                           __nv_bfloat162* __restrict__ lo, int n4)
{
    int i = blockIdx.x * blockDim.x + threadIdx.x;
    if (i >= n4) return;
    float4 x = in[i];
    __nv_bfloat16 h0 = __float2bfloat16(x.x);
    __nv_bfloat16 h1 = __float2bfloat16(x.y);
    __nv_bfloat16 h2 = __float2bfloat16(x.z);
    __nv_bfloat16 h3 = __float2bfloat16(x.w);
    __nv_bfloat16 l0 = __float2bfloat16(x.x - __bfloat162float(h0));
    __nv_bfloat16 l1 = __float2bfloat16(x.y - __bfloat162float(h1));
    __nv_bfloat16 l2 = __float2bfloat16(x.z - __bfloat162float(h2));
    __nv_bfloat16 l3 = __float2bfloat16(x.w - __bfloat162float(h3));
    hi[2 * i + 0] = __nv_bfloat162(h0, h1);
    hi[2 * i + 1] = __nv_bfloat162(h2, h3);
    lo[2 * i + 0] = __nv_bfloat162(l0, l1);
    lo[2 * i + 1] = __nv_bfloat162(l2, l3);
}

// ---------------------------------------------------------------------------
// Split-bf16 tensor-core GEMM: C[M,N] = A[M,K] @ B[N,K]^T (+bias)
// acc = Ahi*Bhi + Ahi*Blo + Alo*Bhi, fp32 accumulate (mma.m16n8k16)
// BM=128, BN=128, BK=32, 2-stage cp.async pipeline, 8 warps (4m x 2n).
// ---------------------------------------------------------------------------
#define BM 128
#define BN 128
#define BKk 32
#define SSTRIDE 40                       // bf16 elems per smem row (80B: conflict-free)
#define TILE_B (BM * SSTRIDE * 2)        // 10240 bytes per matrix tile
#define STAGE_B (4 * TILE_B)             // 40960 bytes per stage
#define GEMM_SMEM (2 * STAGE_B)          // 81920 bytes

__device__ __forceinline__ void cp16(uint32_t d, const void* s) {
    asm volatile("cp.async.cg.shared.global [%0], [%1], 16;\n" :: "r"(d), "l"(s));
}
template<int N_> __device__ __forceinline__ void cpwait() {
    asm volatile("cp.async.wait_group %0;\n" :: "n"(N_));
}
__device__ __forceinline__ void ldm_x4(uint32_t* r, uint32_t a) {
    asm volatile("ldmatrix.sync.aligned.m8n8.x4.shared.b16 {%0,%1,%2,%3}, [%4];\n"
                 : "=r"(r[0]), "=r"(r[1]), "=r"(r[2]), "=r"(r[3]) : "r"(a));
}
__device__ __forceinline__ void mma16816(float* d, const uint32_t* a, const uint32_t* b) {
    asm volatile("mma.sync.aligned.m16n8k16.row.col.f32.bf16.bf16.f32 "
                 "{%0,%1,%2,%3}, {%4,%5,%6,%7}, {%8,%9}, {%0,%1,%2,%3};\n"
                 : "+f"(d[0]), "+f"(d[1]), "+f"(d[2]), "+f"(d[3])
                 : "r"(a[0]), "r"(a[1]), "r"(a[2]), "r"(a[3]), "r"(b[0]), "r"(b[1]));
}

__global__ __launch_bounds__(256, 1)
void gemm_bf16split(const __nv_bfloat16* __restrict__ Ahi,
                    const __nv_bfloat16* __restrict__ Alo,
                    const __nv_bfloat16* __restrict__ Bhi,
                    const __nv_bfloat16* __restrict__ Blo,
                    const float* __restrict__ bias, float* __restrict__ C,
                    int M, int N, int K)
{
    extern __shared__ __nv_bfloat16 smem[];
    const uint32_t smem_u32 = (uint32_t)__cvta_generic_to_shared(smem);

    const int tid = threadIdx.x;
    const int m0 = blockIdx.y * BM;
    const int n0 = blockIdx.x * BN;

    // ---- loader mapping: row = tid&127, 2 contiguous 16B chunks at col (tid>>7)*16
    const int lr = tid & 127;
    const int lc = (tid >> 7) * 16;
    const __nv_bfloat16* pA0 = Ahi + (size_t)(m0 + lr) * K + lc;
    const __nv_bfloat16* pA1 = Alo + (size_t)(m0 + lr) * K + lc;
    const __nv_bfloat16* pB0 = Bhi + (size_t)(n0 + lr) * K + lc;
    const __nv_bfloat16* pB1 = Blo + (size_t)(n0 + lr) * K + lc;
    const uint32_t dst0 = smem_u32 + (uint32_t)(lr * SSTRIDE + lc) * 2;

#define PREFETCH(kt, st) do {                                              \
        uint32_t db = dst0 + (uint32_t)(st) * STAGE_B;                     \
        const __nv_bfloat16* s0 = pA0 + (kt) * BKk;                        \
        const __nv_bfloat16* s1 = pA1 + (kt) * BKk;                        \
        const __nv_bfloat16* s2 = pB0 + (kt) * BKk;                        \
        const __nv_bfloat16* s3 = pB1 + (kt) * BKk;                        \
        cp16(db,                 s0); cp16(db + 16,                s0 + 8);\
        cp16(db + TILE_B,        s1); cp16(db + TILE_B + 16,       s1 + 8);\
        cp16(db + 2 * TILE_B,    s2); cp16(db + 2 * TILE_B + 16,   s2 + 8);\
        cp16(db + 3 * TILE_B,    s3); cp16(db + 3 * TILE_B + 16,   s3 + 8);\
        asm volatile("cp.async.commit_group;\n");                          \
    } while (0)

    // ---- compute mapping
    const int lane = tid & 31;
    const int w  = tid >> 5;
    const int wm = w & 3;      // 4 warps along M (32 rows each)
    const int wn = w >> 2;     // 2 warps along N (64 cols each)

    const uint32_t aoff = smem_u32
        + (uint32_t)((wm * 32 + (lane & 15)) * SSTRIDE + (lane >> 4) * 8) * 2;
    const uint32_t boff = smem_u32 + 2 * TILE_B
        + (uint32_t)((wn * 64 + (lane & 15)) * SSTRIDE + (lane >> 4) * 8) * 2;

    float acc[2][8][4];
#pragma unroll
    for (int i = 0; i < 2; i++)
#pragma unroll
        for (int j = 0; j < 8; j++)
#pragma unroll
            for (int t = 0; t < 4; t++) acc[i][j][t] = 0.f;

    const int KT = K / BKk;
    PREFETCH(0, 0);

    for (int kt = 0; kt < KT; kt++) {
        const int st = kt & 1;
        if (kt + 1 < KT) { PREFETCH(kt + 1, st ^ 1); cpwait<1>(); }
        else             { cpwait<0>(); }
        __syncthreads();

        const uint32_t sb = (uint32_t)st * STAGE_B;
#pragma unroll
        for (int kk = 0; kk < 2; kk++) {
            const uint32_t ko = sb + kk * 32;   // 16 bf16 = 32 bytes
            uint32_t ah[2][4], al[2][4];
            ldm_x4(ah[0], aoff + ko);
            ldm_x4(ah[1], aoff + ko + 16 * SSTRIDE * 2);
            ldm_x4(al[0], aoff + ko + TILE_B);
            ldm_x4(al[1], aoff + ko + TILE_B + 16 * SSTRIDE * 2);
            uint32_t bh[8][2], bl[8][2];
#pragma unroll
            for (int ng = 0; ng < 4; ng++) {
                uint32_t r[4];
                ldm_x4(r, boff + ko + ng * 16 * SSTRIDE * 2);
                bh[2 * ng][0] = r[0]; bh[2 * ng][1] = r[2];
                bh[2 * ng + 1][0] = r[1]; bh[2 * ng + 1][1] = r[3];
                ldm_x4(r, boff + ko + ng * 16 * SSTRIDE * 2 + TILE_B);
                bl[2 * ng][0] = r[0]; bl[2 * ng][1] = r[2];
                bl[2 * ng + 1][0] = r[1]; bl[2 * ng + 1][1] = r[3];
            }
#pragma unroll
            for (int mt = 0; mt < 2; mt++)
#pragma unroll
                for (int nt = 0; nt < 8; nt++) {
                    mma16816(acc[mt][nt], ah[mt], bh[nt]);
                    mma16816(acc[mt][nt], ah[mt], bl[nt]);
                    mma16816(acc[mt][nt], al[mt], bh[nt]);
                }
        }
        __syncthreads();
    }

    // ---- epilogue
    const int gr = lane >> 2;
    const int gc = (lane & 3) * 2;
#pragma unroll
    for (int mt = 0; mt < 2; mt++) {
        const int row = m0 + wm * 32 + mt * 16 + gr;
#pragma unroll
        for (int nt = 0; nt < 8; nt++) {
            const int col = n0 + wn * 64 + nt * 8 + gc;
            float b0 = 0.f, b1 = 0.f;
            if (bias) { b0 = bias[col]; b1 = bias[col + 1]; }
            float2 o0 = make_float2(acc[mt][nt][0] + b0, acc[mt][nt][1] + b1);
            float2 o1 = make_float2(acc[mt][nt][2] + b0, acc[mt][nt][3] + b1);
            *(float2*)(C + (size_t)row * N + col) = o0;
            *(float2*)(C + (size_t)(row + 8) * N + col) = o1;
        }
    }
}

// ---------------------------------------------------------------------------
// Block-local attention (fp32 scalar) — one CTA per (b, blk, head)
// ---------------------------------------------------------------------------
#define ATTN_SMEM (2 * BLKLEN * DK * (int)sizeof(float))   // 66048 bytes

__global__ __launch_bounds__(160, 2)
void blk_attn(const float* __restrict__ Q, const float* __restrict__ Kt,
              const float* __restrict__ Vt, float* __restrict__ O)
{
    extern __shared__ float sm[];
    float* ks = sm;
    float* vs = sm + BLKLEN * DK;

    const int bid = blockIdx.x;
    const int h   = bid & 15;
    const int blk = (bid >> 4) & 31;
    const int b   = bid >> 9;
    const size_t base = ((size_t)b * NLEN + (size_t)blk * BLKLEN) * DIMN + h * DK;
    const int tid = threadIdx.x;

    for (int i = tid; i < BLKLEN * 16; i += 160) {
        const int r = i >> 4, c = i & 15;
        ((float4*)ks)[i] = *(const float4*)(Kt + base + (size_t)r * DIMN + c * 4);
        ((float4*)vs)[i] = *(const float4*)(Vt + base + (size_t)r * DIMN + c * 4);
    }
    __syncthreads();

    if (tid < BLKLEN) {
        float qr[64];
        const float4* qp = (const float4*)(Q + base + (size_t)tid * DIMN);
#pragma unroll
        for (int i = 0; i < 16; i++) {
            float4 t = qp[i];
            qr[4 * i] = t.x; qr[4 * i + 1] = t.y; qr[4 * i + 2] = t.z; qr[4 * i + 3] = t.w;
        }
        float acc[64];
#pragma unroll
        for (int d = 0; d < 64; d++) acc[d] = 0.f;
        float l = 0.f;
        const float scale = 0.125f;

        for (int key = 0; key < BLKLEN; key++) {
            const float4* kp = (const float4*)(ks + key * DK);
            float s0 = 0.f, s1 = 0.f, s2 = 0.f, s3 = 0.f;
#pragma unroll
            for (int i = 0; i < 16; i++) {
                float4 kv = kp[i];
                s0 += qr[4 * i] * kv.x;     s1 += qr[4 * i + 1] * kv.y;
                s2 += qr[4 * i + 2] * kv.z; s3 += qr[4 * i + 3] * kv.w;
            }
            const float p = __expf(((s0 + s1) + (s2 + s3)) * scale);
            l += p;
            const float4* vp = (const float4*)(vs + key * DK);
#pragma unroll
            for (int i = 0; i < 16; i++) {
                float4 vv = vp[i];
                acc[4 * i] += p * vv.x;     acc[4 * i + 1] += p * vv.y;
                acc[4 * i + 2] += p * vv.z; acc[4 * i + 3] += p * vv.w;
            }
        }

        const float rl = 1.0f / l;
        float4* op = (float4*)(O + base + (size_t)tid * DIMN);
#pragma unroll
        for (int i = 0; i < 16; i++) {
            float4 t;
            t.x = acc[4 * i] * rl;     t.y = acc[4 * i + 1] * rl;
            t.z = acc[4 * i + 2] * rl; t.w = acc[4 * i + 3] * rl;
            op[i] = t;
        }
    }
}

// ---------------------------------------------------------------------------
// Global attention over first token of each block — one CTA per (b, h)
// ---------------------------------------------------------------------------
__global__ __launch_bounds__(32)
void glob_attn(const float* __restrict__ Q, const float* __restrict__ Kt,
               const float* __restrict__ Vt, float* __restrict__ O)
{
    __shared__ float ks[NB * DK];
    __shared__ float vs[NB * DK];
    const int b = blockIdx.x >> 4;
    const int h = blockIdx.x & 15;
    const int tid = threadIdx.x;

    const size_t rowbase = ((size_t)b * NLEN + (size_t)tid * BLKLEN) * DIMN + h * DK;
#pragma unroll
    for (int i = 0; i < 16; i++) {
        ((float4*)(ks + tid * DK))[i] = *(const float4*)(Kt + rowbase + i * 4);
        ((float4*)(vs + tid * DK))[i] = *(const float4*)(Vt + rowbase + i * 4);
    }
    __syncthreads();

    float qr[64];
    const float4* qp = (const float4*)(Q + rowbase);
#pragma unroll
    for (int i = 0; i < 16; i++) {
        float4 t = qp[i];
        qr[4 * i] = t.x; qr[4 * i + 1] = t.y; qr[4 * i + 2] = t.z; qr[4 * i + 3] = t.w;
    }
    float acc[64];
#pragma unroll
    for (int d = 0; d < 64; d++) acc[d] = 0.f;
    float l = 0.f;
    const float scale = 0.125f;

    for (int key = 0; key < NB; key++) {
        const float4* kp = (const float4*)(ks + key * DK);
        float s0 = 0.f, s1 = 0.f, s2 = 0.f, s3 = 0.f;
#pragma unroll
        for (int i = 0; i < 16; i++) {
            float4 kv = kp[i];
            s0 += qr[4 * i] * kv.x;     s1 += qr[4 * i + 1] * kv.y;
            s2 += qr[4 * i + 2] * kv.z; s3 += qr[4 * i + 3] * kv.w;
        }
        const float p = __expf(((s0 + s1) + (s2 + s3)) * scale);
        l += p;
        const float4* vp = (const float4*)(vs + key * DK);
#pragma unroll
        for (int i = 0; i < 16; i++) {
            float4 vv = vp[i];
            acc[4 * i] += p * vv.x;     acc[4 * i + 1] += p * vv.y;
            acc[4 * i + 2] += p * vv.z; acc[4 * i + 3] += p * vv.w;
        }
    }

    const float rl = 1.0f / l;
    float4* op = (float4*)(O + rowbase);
#pragma unroll
    for (int i = 0; i < 16; i++) {
        float4 t = op[i];
        t.x += acc[4 * i] * rl;     t.y += acc[4 * i + 1] * rl;
        t.z += acc[4 * i + 2] * rl; t.w += acc[4 * i + 3] * rl;
        op[i] = t;
    }
}

// ---------------------------------------------------------------------------
extern "C" void kernel_launch(void* const* d_in, const int* in_sizes, int n_in,
                              void* d_out, int out_size)
{
    const float* x  = (const float*)d_in[0];
    const float* Wq = (const float*)d_in[1];
    const float* Wk = (const float*)d_in[2];
    const float* Wv = (const float*)d_in[3];
    const float* Wo = (const float*)d_in[4];
    const float* bo = (const float*)d_in[5];
    float* out = (float*)d_out;

    float *q, *k, *v, *attn;
    __nv_bfloat16 *xhi, *xlo, *ahi, *alo, *whi, *wlo;
    cudaGetSymbolAddress((void**)&q,    g_q);
    cudaGetSymbolAddress((void**)&k,    g_k);
    cudaGetSymbolAddress((void**)&v,    g_v);
    cudaGetSymbolAddress((void**)&attn, g_attn);
    cudaGetSymbolAddress((void**)&xhi,  g_xhi);
    cudaGetSymbolAddress((void**)&xlo,  g_xlo);
    cudaGetSymbolAddress((void**)&ahi,  g_ahi);
    cudaGetSymbolAddress((void**)&alo,  g_alo);
    cudaGetSymbolAddress((void**)&whi,  g_whi);
    cudaGetSymbolAddress((void**)&wlo,  g_wlo);

    cudaFuncSetAttribute(gemm_bf16split, cudaFuncAttributeMaxDynamicSharedMemorySize,
                         GEMM_SMEM);
    cudaFuncSetAttribute(blk_attn, cudaFuncAttributeMaxDynamicSharedMemorySize,
                         ATTN_SMEM);

    const int W = DIMN * DIMN;          // 1M elems per weight
    const int n4x = TOK * DIMN / 4;
    const int n4w = W / 4;

    // fp32 -> split bf16
    cvt_split4<<<(n4x + 255) / 256, 256>>>((const float4*)x,
        (__nv_bfloat162*)xhi, (__nv_bfloat162*)xlo, n4x);
    cvt_split4<<<(n4w + 255) / 256, 256>>>((const float4*)Wq,
        (__nv_bfloat162*)(whi + 0 * W), (__nv_bfloat162*)(wlo + 0 * W), n4w);
    cvt_split4<<<(n4w + 255) / 256, 256>>>((const float4*)Wk,
        (__nv_bfloat162*)(whi + 1 * W), (__nv_bfloat162*)(wlo + 1 * W), n4w);
    cvt_split4<<<(n4w + 255) / 256, 256>>>((const float4*)Wv,
        (__nv_bfloat162*)(whi + 2 * W), (__nv_bfloat162*)(wlo + 2 * W), n4w);
    cvt_split4<<<(n4w + 255) / 256, 256>>>((const float4*)Wo,
        (__nv_bfloat162*)(whi + 3 * W), (__nv_bfloat162*)(wlo + 3 * W), n4w);

    dim3 gP(DIMN / BN, TOK / BM);   // (8, 129)
    gemm_bf16split<<<gP, 256, GEMM_SMEM>>>(xhi, xlo, whi + 0 * W, wlo + 0 * W,
                                           nullptr, q, TOK, DIMN, DIMN);
    gemm_bf16split<<<gP, 256, GEMM_SMEM>>>(xhi, xlo, whi + 1 * W, wlo + 1 * W,
                                           nullptr, k, TOK, DIMN, DIMN);
    gemm_bf16split<<<gP, 256, GEMM_SMEM>>>(xhi, xlo, whi + 2 * W, wlo + 2 * W,
                                           nullptr, v, TOK, DIMN, DIMN);

    blk_attn<<<B_SZ * NB * HEADS, 160, ATTN_SMEM>>>(q, k, v, attn);
    glob_attn<<<B_SZ * HEADS, 32>>>(q, k, v, attn);

    cvt_split4<<<(n4x + 255) / 256, 256>>>((const float4*)attn,
        (__nv_bfloat162*)ahi, (__nv_bfloat162*)alo, n4x);

    gemm_bf16split<<<gP, 256, GEMM_SMEM>>>(ahi, alo, whi + 3 * W, wlo + 3 * W,
                                           bo, out, TOK, DIMN, DIMN);
}

// round 4
// speedup vs baseline: 13.3180x; 1.5927x over previous
#include <cuda_runtime.h>
#include <cuda_fp16.h>
#include <cstdint>
#include <math.h>

#define B_SZ   4
#define NLEN   4128
#define DIMN   1024
#define HEADS  16
#define BLKLEN 129
#define NB     32
#define DK     64
#define TOK    (B_SZ * NLEN)   // 16512

// ---------------- scratch (device globals: allocation-free) ----------------
__device__ __half g_xhi[TOK * DIMN];
__device__ __half g_xlo[TOK * DIMN];
__device__ __half g_q16[TOK * DIMN];
__device__ __half g_k16[TOK * DIMN];
__device__ __half g_v16[TOK * DIMN];
__device__ __half g_ahi[TOK * DIMN];
__device__ __half g_alo[TOK * DIMN];
__device__ __half g_w16[4 * DIMN * DIMN];
__device__ float  g_glob[B_SZ * NB * HEADS * DK];

// ============================ helpers ======================================
__device__ __forceinline__ uint32_t smem_u32(const void* p) {
    return (uint32_t)__cvta_generic_to_shared(p);
}
__device__ __forceinline__ void cp16(uint32_t d, const void* s) {
    asm volatile("cp.async.cg.shared.global [%0], [%1], 16;\n" :: "r"(d), "l"(s));
}
__device__ __forceinline__ void cp_commit() {
    asm volatile("cp.async.commit_group;\n");
}
template<int N_> __device__ __forceinline__ void cpwait() {
    asm volatile("cp.async.wait_group %0;\n" :: "n"(N_));
}
__device__ __forceinline__ void ldm_x4(uint32_t* r, uint32_t a) {
    asm volatile("ldmatrix.sync.aligned.m8n8.x4.shared.b16 {%0,%1,%2,%3}, [%4];\n"
                 : "=r"(r[0]), "=r"(r[1]), "=r"(r[2]), "=r"(r[3]) : "r"(a));
}
__device__ __forceinline__ void ldm_x4_t(uint32_t* r, uint32_t a) {
    asm volatile("ldmatrix.sync.aligned.m8n8.x4.trans.shared.b16 {%0,%1,%2,%3}, [%4];\n"
                 : "=r"(r[0]), "=r"(r[1]), "=r"(r[2]), "=r"(r[3]) : "r"(a));
}
__device__ __forceinline__ void mma_h(float* d, const uint32_t* a,
                                      uint32_t b0, uint32_t b1) {
    asm volatile("mma.sync.aligned.m16n8k16.row.col.f32.f16.f16.f32 "
                 "{%0,%1,%2,%3}, {%4,%5,%6,%7}, {%8,%9}, {%0,%1,%2,%3};\n"
                 : "+f"(d[0]), "+f"(d[1]), "+f"(d[2]), "+f"(d[3])
                 : "r"(a[0]), "r"(a[1]), "r"(a[2]), "r"(a[3]), "r"(b0), "r"(b1));
}
__device__ __forceinline__ uint32_t packh2(float x, float y) {
    __half2 h = __floats2half2_rn(x, y);
    return *(uint32_t*)&h;
}

// ---------------------------------------------------------------------------
// conversions
// ---------------------------------------------------------------------------
__global__ void cvt_split_h4(const float4* __restrict__ in,
                             __half2* __restrict__ hi,
                             __half2* __restrict__ lo, int n4)
{
    int i = blockIdx.x * blockDim.x + threadIdx.x;
    if (i >= n4) return;
    float4 x = in[i];
    __half h0 = __float2half(x.x), h1 = __float2half(x.y);
    __half h2 = __float2half(x.z), h3 = __float2half(x.w);
    __half l0 = __float2half(x.x - __half2float(h0));
    __half l1 = __float2half(x.y - __half2float(h1));
    __half l2 = __float2half(x.z - __half2float(h2));
    __half l3 = __float2half(x.w - __half2float(h3));
    hi[2 * i + 0] = __halves2half2(h0, h1);
    hi[2 * i + 1] = __halves2half2(h2, h3);
    lo[2 * i + 0] = __halves2half2(l0, l1);
    lo[2 * i + 1] = __halves2half2(l2, l3);
}

__global__ void cvt_h4(const float4* __restrict__ in, __half2* __restrict__ out, int n4)
{
    int i = blockIdx.x * blockDim.x + threadIdx.x;
    if (i >= n4) return;
    float4 x = in[i];
    out[2 * i + 0] = __floats2half2_rn(x.x, x.y);
    out[2 * i + 1] = __floats2half2_rn(x.z, x.w);
}

// ---------------------------------------------------------------------------
// 2-term split-fp16 HMMA GEMM: C[M,N] = (Ahi+Alo)[M,K] @ B16[N,K]^T
// BM=BN=128, BK=32, 2-stage cp.async. 3 smem tiles/stage (Ahi, Alo, B).
// Consecutive MMAs hit different accumulators (latency-tolerant order).
// ---------------------------------------------------------------------------
#define SSTRIDE 40
#define TILE_B (128 * SSTRIDE * 2)   // 10240 B
#define STAGE_B (3 * TILE_B)         // 30720 B
#define GEMM_SMEM (2 * STAGE_B)      // 61440 B
#define KT32 (DIMN / 32)             // 32

struct GemmFrags {
    uint32_t ah[2][4], al[2][4], b[8][2];
};

__device__ __forceinline__ void gemm_core(
    const __half* pA0, const __half* pA1, const __half* pB,
    uint32_t smem, uint32_t dst0, uint32_t aoff, uint32_t boff,
    float acc[2][8][4])
{
#define PREF(kt, st) do {                                                   \
        uint32_t db = dst0 + (uint32_t)(st) * STAGE_B;                      \
        const __half* s0 = pA0 + (kt) * 32;                                 \
        const __half* s1 = pA1 + (kt) * 32;                                 \
        const __half* s2 = pB + (kt) * 32;                                  \
        cp16(db,              s0); cp16(db + 16,              s0 + 8);      \
        cp16(db + TILE_B,     s1); cp16(db + TILE_B + 16,     s1 + 8);      \
        cp16(db + 2 * TILE_B, s2); cp16(db + 2 * TILE_B + 16, s2 + 8);      \
        cp_commit();                                                        \
    } while (0)

    PREF(0, 0);
    for (int kt = 0; kt < KT32; kt++) {
        const int st = kt & 1;
        if (kt + 1 < KT32) { PREF(kt + 1, st ^ 1); cpwait<1>(); }
        else               { cpwait<0>(); }
        __syncthreads();

        const uint32_t sb = (uint32_t)st * STAGE_B;
#pragma unroll
        for (int kk = 0; kk < 2; kk++) {
            const uint32_t ko = sb + kk * 32;
            GemmFrags f;
            ldm_x4(f.ah[0], aoff + ko);
            ldm_x4(f.ah[1], aoff + ko + 16 * SSTRIDE * 2);
            ldm_x4(f.al[0], aoff + ko + TILE_B);
            ldm_x4(f.al[1], aoff + ko + TILE_B + 16 * SSTRIDE * 2);
#pragma unroll
            for (int ng = 0; ng < 4; ng++) {
                uint32_t r[4];
                ldm_x4(r, boff + ko + ng * 16 * SSTRIDE * 2);
                f.b[2 * ng][0] = r[0]; f.b[2 * ng][1] = r[2];
                f.b[2 * ng + 1][0] = r[1]; f.b[2 * ng + 1][1] = r[3];
            }
#pragma unroll
            for (int mt = 0; mt < 2; mt++)
#pragma unroll
                for (int nt = 0; nt < 8; nt++)
                    mma_h(acc[mt][nt], f.ah[mt], f.b[nt][0], f.b[nt][1]);
#pragma unroll
            for (int mt = 0; mt < 2; mt++)
#pragma unroll
                for (int nt = 0; nt < 8; nt++)
                    mma_h(acc[mt][nt], f.al[mt], f.b[nt][0], f.b[nt][1]);
        }
        __syncthreads();
    }
#undef PREF
}

// fused QKV variant: z selects weight + fp16 output
__global__ __launch_bounds__(256, 1)
void gemm_qkv(const __half* __restrict__ Ahi, const __half* __restrict__ Alo,
              const __half* __restrict__ W0, const __half* __restrict__ W1,
              const __half* __restrict__ W2,
              __half* __restrict__ O0, __half* __restrict__ O1,
              __half* __restrict__ O2)
{
    extern __shared__ __half smemh[];
    const uint32_t smem = smem_u32(smemh);
    const int tid = threadIdx.x, lane = tid & 31, w = tid >> 5;
    const int m0 = blockIdx.y * 128, n0 = blockIdx.x * 128;
    const __half* Bm = (blockIdx.z == 0) ? W0 : (blockIdx.z == 1 ? W1 : W2);
    __half* C = (blockIdx.z == 0) ? O0 : (blockIdx.z == 1 ? O1 : O2);

    const int lr = tid & 127, lc = (tid >> 7) * 16;
    const __half* pA0 = Ahi + (size_t)(m0 + lr) * DIMN + lc;
    const __half* pA1 = Alo + (size_t)(m0 + lr) * DIMN + lc;
    const __half* pB  = Bm  + (size_t)(n0 + lr) * DIMN + lc;
    const uint32_t dst0 = smem + (uint32_t)(lr * SSTRIDE + lc) * 2;

    const int wm = w & 3, wn = w >> 2;
    const uint32_t aoff = smem +
        (uint32_t)((wm * 32 + (lane & 15)) * SSTRIDE + (lane >> 4) * 8) * 2;
    const uint32_t boff = smem + 2 * TILE_B +
        (uint32_t)((wn * 64 + (lane & 15)) * SSTRIDE + (lane >> 4) * 8) * 2;

    float acc[2][8][4];
#pragma unroll
    for (int i = 0; i < 2; i++)
#pragma unroll
        for (int j = 0; j < 8; j++)
#pragma unroll
            for (int t = 0; t < 4; t++) acc[i][j][t] = 0.f;

    gemm_core(pA0, pA1, pB, smem, dst0, aoff, boff, acc);

    const int gr = lane >> 2, gc = (lane & 3) * 2;
#pragma unroll
    for (int mt = 0; mt < 2; mt++) {
        const int row = m0 + wm * 32 + mt * 16 + gr;
#pragma unroll
        for (int nt = 0; nt < 8; nt++) {
            const int col = n0 + wn * 64 + nt * 8 + gc;
            __half2 h0 = __floats2half2_rn(acc[mt][nt][0], acc[mt][nt][1]);
            __half2 h1 = __floats2half2_rn(acc[mt][nt][2], acc[mt][nt][3]);
            *(__half2*)(C + (size_t)row * DIMN + col) = h0;
            *(__half2*)(C + (size_t)(row + 8) * DIMN + col) = h1;
        }
    }
}

// final GEMM: fp32 out + bias
__global__ __launch_bounds__(256, 1)
void gemm_out(const __half* __restrict__ Ahi, const __half* __restrict__ Alo,
              const __half* __restrict__ Bm, const float* __restrict__ bias,
              float* __restrict__ C)
{
    extern __shared__ __half smemh[];
    const uint32_t smem = smem_u32(smemh);
    const int tid = threadIdx.x, lane = tid & 31, w = tid >> 5;
    const int m0 = blockIdx.y * 128, n0 = blockIdx.x * 128;

    const int lr = tid & 127, lc = (tid >> 7) * 16;
    const __half* pA0 = Ahi + (size_t)(m0 + lr) * DIMN + lc;
    const __half* pA1 = Alo + (size_t)(m0 + lr) * DIMN + lc;
    const __half* pB  = Bm  + (size_t)(n0 + lr) * DIMN + lc;
    const uint32_t dst0 = smem + (uint32_t)(lr * SSTRIDE + lc) * 2;

    const int wm = w & 3, wn = w >> 2;
    const uint32_t aoff = smem +
        (uint32_t)((wm * 32 + (lane & 15)) * SSTRIDE + (lane >> 4) * 8) * 2;
    const uint32_t boff = smem + 2 * TILE_B +
        (uint32_t)((wn * 64 + (lane & 15)) * SSTRIDE + (lane >> 4) * 8) * 2;

    float acc[2][8][4];
#pragma unroll
    for (int i = 0; i < 2; i++)
#pragma unroll
        for (int j = 0; j < 8; j++)
#pragma unroll
            for (int t = 0; t < 4; t++) acc[i][j][t] = 0.f;

    gemm_core(pA0, pA1, pB, smem, dst0, aoff, boff, acc);

    const int gr = lane >> 2, gc = (lane & 3) * 2;
#pragma unroll
    for (int mt = 0; mt < 2; mt++) {
        const int row = m0 + wm * 32 + mt * 16 + gr;
#pragma unroll
        for (int nt = 0; nt < 8; nt++) {
            const int col = n0 + wn * 64 + nt * 8 + gc;
            const float b0 = bias[col], b1 = bias[col + 1];
            *(float2*)(C + (size_t)row * DIMN + col) =
                make_float2(acc[mt][nt][0] + b0, acc[mt][nt][1] + b1);
            *(float2*)(C + (size_t)(row + 8) * DIMN + col) =
                make_float2(acc[mt][nt][2] + b0, acc[mt][nt][3] + b1);
        }
    }
}

// ---------------------------------------------------------------------------
// HMMA block-local attention. One CTA per (b, blk, head), 9 warps.
// S = QK^T (fp16 mma, fp32 acc), no-max softmax, O = P·V, epilogue writes
// (hi,lo) fp16 split of output (+ global-attention add on row 0).
// ---------------------------------------------------------------------------
#define AQS 72                              // smem row stride (halfs)
#define AT_SMEM (3 * 144 * AQS * 2)         // 62208 B

__global__ __launch_bounds__(288, 1)
void blk_attn_tc(const __half* __restrict__ q16, const __half* __restrict__ k16,
                 const __half* __restrict__ v16, const float* __restrict__ glob,
                 __half* __restrict__ ahi, __half* __restrict__ alo)
{
    extern __shared__ __half sh[];
    __half* Qs = sh;
    __half* Ks = sh + 144 * AQS;
    __half* Vs = Ks + 144 * AQS;

    const int bid = blockIdx.x;
    const int h = bid & 15, blk = (bid >> 4) & 31, b = bid >> 9;
    const size_t gbase = ((size_t)(b * NLEN + blk * BLKLEN)) * DIMN + h * DK;
    const int tid = threadIdx.x, lane = tid & 31, wid = tid >> 5;

    const uint4 z4 = make_uint4(0, 0, 0, 0);
    for (int i = tid; i < 144 * 8; i += 288) {
        const int r = i >> 3, c = (i & 7) * 8;
        uint4 qv = z4, kv = z4, vv = z4;
        if (r < BLKLEN) {
            const size_t g = gbase + (size_t)r * DIMN + c;
            qv = *(const uint4*)(q16 + g);
            kv = *(const uint4*)(k16 + g);
            vv = *(const uint4*)(v16 + g);
        }
        *(uint4*)&Qs[r * AQS + c] = qv;
        *(uint4*)&Ks[r * AQS + c] = kv;
        *(uint4*)&Vs[r * AQS + c] = vv;
    }
    __syncthreads();

    const int m0 = wid * 16;          // 9 warps -> 9 m-tiles (rows 0..143)
    const int cbase = (lane & 3) * 2;
    const int gr = lane >> 2;

    // A frags (Q) for the 4 k-steps of DK=64
    uint32_t aq[4][4];
#pragma unroll
    for (int ks = 0; ks < 4; ks++) {
        uint32_t ad = smem_u32(&Qs[(m0 + (lane & 15)) * AQS + ks * 16 + (lane >> 4) * 8]);
        ldm_x4(aq[ks], ad);
    }

    // S = Q K^T : 17 n8-tiles (136 key slots, >=129 zero-padded)
    float sacc[17][4];
#pragma unroll
    for (int j = 0; j < 17; j++)
#pragma unroll
        for (int t = 0; t < 4; t++) sacc[j][t] = 0.f;

#pragma unroll
    for (int ks = 0; ks < 4; ks++) {
#pragma unroll
        for (int jp = 0; jp < 8; jp++) {        // tiles 0..15
            uint32_t r[4];
            uint32_t ad = smem_u32(&Ks[(jp * 16 + (lane & 15)) * AQS
                                       + ks * 16 + (lane >> 4) * 8]);
            ldm_x4(r, ad);
            mma_h(sacc[2 * jp],     aq[ks], r[0], r[2]);
            mma_h(sacc[2 * jp + 1], aq[ks], r[1], r[3]);
        }
        {   // tile 16 (keys 128..135)
            uint32_t r[4];
            uint32_t ad = smem_u32(&Ks[(128 + (lane & 15)) * AQS
                                       + ks * 16 + (lane >> 4) * 8]);
            ldm_x4(r, ad);
            mma_h(sacc[16], aq[ks], r[0], r[2]);
        }
    }

    // softmax (no max-subtraction; scores*scale ~ N(0,1))
    const float scale = 0.125f;
    float l0 = 0.f, l1 = 0.f;
#pragma unroll
    for (int j = 0; j < 17; j++) {
        const int c0 = j * 8 + cbase;
        const bool v0 = c0 < BLKLEN, v1 = (c0 + 1) < BLKLEN;
        float p0 = v0 ? __expf(sacc[j][0] * scale) : 0.f;
        float p1 = v1 ? __expf(sacc[j][1] * scale) : 0.f;
        float p2 = v0 ? __expf(sacc[j][2] * scale) : 0.f;
        float p3 = v1 ? __expf(sacc[j][3] * scale) : 0.f;
        sacc[j][0] = p0; sacc[j][1] = p1; sacc[j][2] = p2; sacc[j][3] = p3;
        l0 += p0 + p1; l1 += p2 + p3;
    }
    l0 += __shfl_xor_sync(0xFFFFFFFFu, l0, 1);
    l0 += __shfl_xor_sync(0xFFFFFFFFu, l0, 2);
    l1 += __shfl_xor_sync(0xFFFFFFFFu, l1, 1);
    l1 += __shfl_xor_sync(0xFFFFFFFFu, l1, 2);

    // O = P V  (9 k-steps of 16 keys; V rows >=129 are zero)
    float oacc[8][4];
#pragma unroll
    for (int g = 0; g < 8; g++)
#pragma unroll
        for (int t = 0; t < 4; t++) oacc[g][t] = 0.f;

    const int vmat = lane >> 3;
#pragma unroll
    for (int kp = 0; kp < 9; kp++) {
        uint32_t pa[4];
        const int t0 = 2 * kp, t1 = 2 * kp + 1;
        pa[0] = packh2(sacc[t0][0], sacc[t0][1]);
        pa[1] = packh2(sacc[t0][2], sacc[t0][3]);
        if (t1 < 17) {
            pa[2] = packh2(sacc[t1][0], sacc[t1][1]);
            pa[3] = packh2(sacc[t1][2], sacc[t1][3]);
        } else { pa[2] = 0u; pa[3] = 0u; }
#pragma unroll
        for (int g = 0; g < 4; g++) {
            uint32_t r[4];
            uint32_t ad = smem_u32(&Vs[(kp * 16 + (vmat & 1) * 8 + (lane & 7)) * AQS
                                       + g * 16 + (vmat >> 1) * 8]);
            ldm_x4_t(r, ad);
            mma_h(oacc[2 * g],     pa, r[0], r[1]);
            mma_h(oacc[2 * g + 1], pa, r[2], r[3]);
        }
    }

    // epilogue: normalize, add global-attention on row 0, split-write fp16
    const float rl0 = 1.0f / l0, rl1 = 1.0f / l1;
    const int r0 = m0 + gr, r1 = r0 + 8;
    const float* gp = glob + (((size_t)(b * NB + blk) * HEADS) + h) * DK;
#pragma unroll
    for (int g = 0; g < 8; g++) {
        const int col = g * 8 + cbase;
        float o0 = oacc[g][0] * rl0, o1 = oacc[g][1] * rl0;
        float o2 = oacc[g][2] * rl1, o3 = oacc[g][3] * rl1;
        if (r0 == 0) { o0 += gp[col]; o1 += gp[col + 1]; }
        if (r0 < BLKLEN) {
            __half h0 = __float2half(o0), h1 = __float2half(o1);
            __half e0 = __float2half(o0 - __half2float(h0));
            __half e1 = __float2half(o1 - __half2float(h1));
            *(__half2*)(ahi + gbase + (size_t)r0 * DIMN + col) = __halves2half2(h0, h1);
            *(__half2*)(alo + gbase + (size_t)r0 * DIMN + col) = __halves2half2(e0, e1);
        }
        if (r1 < BLKLEN) {
            __half h2 = __float2half(o2), h3 = __float2half(o3);
            __half e2 = __float2half(o2 - __half2float(h2));
            __half e3 = __float2half(o3 - __half2float(h3));
            *(__half2*)(ahi + gbase + (size_t)r1 * DIMN + col) = __halves2half2(h2, h3);
            *(__half2*)(alo + gbase + (size_t)r1 * DIMN + col) = __halves2half2(e2, e3);
        }
    }
}

// ---------------------------------------------------------------------------
// Global attention over first tokens (fp16 in, fp32 out to g_glob)
// ---------------------------------------------------------------------------
__global__ __launch_bounds__(32)
void glob_attn_h(const __half* __restrict__ q16, const __half* __restrict__ k16,
                 const __half* __restrict__ v16, float* __restrict__ glob)
{
    __shared__ float ks[NB * DK];
    __shared__ float vs[NB * DK];
    const int b = blockIdx.x >> 4;
    const int h = blockIdx.x & 15;
    const int tid = threadIdx.x;

    const size_t rowbase = ((size_t)(b * NLEN + tid * BLKLEN)) * DIMN + h * DK;
#pragma unroll
    for (int i = 0; i < 8; i++) {
        __half2 kk = *(const __half2*)(k16 + rowbase + i * 8);
        __half2 k2 = *(const __half2*)(k16 + rowbase + i * 8 + 2);
        __half2 k4 = *(const __half2*)(k16 + rowbase + i * 8 + 4);
        __half2 k6 = *(const __half2*)(k16 + rowbase + i * 8 + 6);
        float2 f0 = __half22float2(kk), f1 = __half22float2(k2);
        float2 f2 = __half22float2(k4), f3 = __half22float2(k6);
        ks[tid * DK + i * 8 + 0] = f0.x; ks[tid * DK + i * 8 + 1] = f0.y;
        ks[tid * DK + i * 8 + 2] = f1.x; ks[tid * DK + i * 8 + 3] = f1.y;
        ks[tid * DK + i * 8 + 4] = f2.x; ks[tid * DK + i * 8 + 5] = f2.y;
        ks[tid * DK + i * 8 + 6] = f3.x; ks[tid * DK + i * 8 + 7] = f3.y;
        __half2 vv = *(const __half2*)(v16 + rowbase + i * 8);
        __half2 v2 = *(const __half2*)(v16 + rowbase + i * 8 + 2);
        __half2 v4 = *(const __half2*)(v16 + rowbase + i * 8 + 4);
        __half2 v6 = *(const __half2*)(v16 + rowbase + i * 8 + 6);
        f0 = __half22float2(vv); f1 = __half22float2(v2);
        f2 = __half22float2(v4); f3 = __half22float2(v6);
        vs[tid * DK + i * 8 + 0] = f0.x; vs[tid * DK + i * 8 + 1] = f0.y;
        vs[tid * DK + i * 8 + 2] = f1.x; vs[tid * DK + i * 8 + 3] = f1.y;
        vs[tid * DK + i * 8 + 4] = f2.x; vs[tid * DK + i * 8 + 5] = f2.y;
        vs[tid * DK + i * 8 + 6] = f3.x; vs[tid * DK + i * 8 + 7] = f3.y;
    }
    __syncthreads();

    float qr[DK];
#pragma unroll
    for (int i = 0; i < DK / 2; i++) {
        float2 f = __half22float2(*(const __half2*)(q16 + rowbase + 2 * i));
        qr[2 * i] = f.x; qr[2 * i + 1] = f.y;
    }
    float acc[DK];
#pragma unroll
    for (int d = 0; d < DK; d++) acc[d] = 0.f;
    float l = 0.f;
    const float scale = 0.125f;

    for (int key = 0; key < NB; key++) {
        const float* kp = ks + key * DK;
        float s = 0.f;
#pragma unroll
        for (int i = 0; i < DK; i++) s += qr[i] * kp[i];
        const float p = __expf(s * scale);
        l += p;
        const float* vp = vs + key * DK;
#pragma unroll
        for (int i = 0; i < DK; i++) acc[i] += p * vp[i];
    }

    const float rl = 1.0f / l;
    float* op = glob + (((size_t)(b * NB + tid) * HEADS) + h) * DK;
#pragma unroll
    for (int i = 0; i < DK; i++) op[i] = acc[i] * rl;
}

// ---------------------------------------------------------------------------
extern "C" void kernel_launch(void* const* d_in, const int* in_sizes, int n_in,
                              void* d_out, int out_size)
{
    const float* x  = (const float*)d_in[0];
    const float* Wq = (const float*)d_in[1];
    const float* Wk = (const float*)d_in[2];
    const float* Wv = (const float*)d_in[3];
    const float* Wo = (const float*)d_in[4];
    const float* bo = (const float*)d_in[5];
    float* out = (float*)d_out;

    __half *xhi, *xlo, *q16, *k16, *v16, *ahi, *alo, *w16;
    float* glob;
    cudaGetSymbolAddress((void**)&xhi, g_xhi);
    cudaGetSymbolAddress((void**)&xlo, g_xlo);
    cudaGetSymbolAddress((void**)&q16, g_q16);
    cudaGetSymbolAddress((void**)&k16, g_k16);
    cudaGetSymbolAddress((void**)&v16, g_v16);
    cudaGetSymbolAddress((void**)&ahi, g_ahi);
    cudaGetSymbolAddress((void**)&alo, g_alo);
    cudaGetSymbolAddress((void**)&w16, g_w16);
    cudaGetSymbolAddress((void**)&glob, g_glob);

    cudaFuncSetAttribute(gemm_qkv, cudaFuncAttributeMaxDynamicSharedMemorySize, GEMM_SMEM);
    cudaFuncSetAttribute(gemm_out, cudaFuncAttributeMaxDynamicSharedMemorySize, GEMM_SMEM);
    cudaFuncSetAttribute(blk_attn_tc, cudaFuncAttributeMaxDynamicSharedMemorySize, AT_SMEM);

    const int W = DIMN * DIMN;
    const int n4x = TOK * DIMN / 4;
    const int n4w = W / 4;

    cvt_split_h4<<<(n4x + 255) / 256, 256>>>((const float4*)x,
        (__half2*)xhi, (__half2*)xlo, n4x);
    cvt_h4<<<(n4w + 255) / 256, 256>>>((const float4*)Wq, (__half2*)(w16 + 0 * W), n4w);
    cvt_h4<<<(n4w + 255) / 256, 256>>>((const float4*)Wk, (__half2*)(w16 + 1 * W), n4w);
    cvt_h4<<<(n4w + 255) / 256, 256>>>((const float4*)Wv, (__half2*)(w16 + 2 * W), n4w);
    cvt_h4<<<(n4w + 255) / 256, 256>>>((const float4*)Wo, (__half2*)(w16 + 3 * W), n4w);

    dim3 gQKV(DIMN / 128, TOK / 128, 3);   // (8, 129, 3)
    gemm_qkv<<<gQKV, 256, GEMM_SMEM>>>(xhi, xlo,
        w16 + 0 * W, w16 + 1 * W, w16 + 2 * W, q16, k16, v16);

    glob_attn_h<<<B_SZ * HEADS, 32>>>(q16, k16, v16, glob);

    blk_attn_tc<<<B_SZ * NB * HEADS, 288, AT_SMEM>>>(q16, k16, v16, glob, ahi, alo);

    dim3 gO(DIMN / 128, TOK / 128);        // (8, 129)
    gemm_out<<<gO, 256, GEMM_SMEM>>>(ahi, alo, w16 + 3 * W, bo, out);
}

// round 6
// speedup vs baseline: 21.6362x; 1.6246x over previous
#include <cuda_runtime.h>
#include <cuda_fp16.h>
#include <cstdint>
#include <math.h>

#define B_SZ   4
#define NLEN   4128
#define DIMN   1024
#define HEADS  16
#define BLKLEN 129
#define NB     32
#define DK     64
#define TOK    (B_SZ * NLEN)   // 16512

// ---------------- scratch (device globals: allocation-free) ----------------
__device__ __half g_x16[TOK * DIMN];
__device__ __half g_q16[TOK * DIMN];
__device__ __half g_k16[TOK * DIMN];
__device__ __half g_v16[TOK * DIMN];
__device__ __half g_a16[TOK * DIMN];
__device__ __half g_w16[4 * DIMN * DIMN];
__device__ float  g_glob[B_SZ * NB * HEADS * DK];

// ============================ helpers ======================================
__device__ __forceinline__ uint32_t smem_u32(const void* p) {
    return (uint32_t)__cvta_generic_to_shared(p);
}
__device__ __forceinline__ void cp16(uint32_t d, const void* s) {
    asm volatile("cp.async.cg.shared.global [%0], [%1], 16;\n" :: "r"(d), "l"(s));
}
__device__ __forceinline__ void cp_commit() {
    asm volatile("cp.async.commit_group;\n");
}
template<int N_> __device__ __forceinline__ void cpwait() {
    asm volatile("cp.async.wait_group %0;\n" :: "n"(N_));
}
__device__ __forceinline__ void ldm_x4(uint32_t* r, uint32_t a) {
    asm volatile("ldmatrix.sync.aligned.m8n8.x4.shared.b16 {%0,%1,%2,%3}, [%4];\n"
                 : "=r"(r[0]), "=r"(r[1]), "=r"(r[2]), "=r"(r[3]) : "r"(a));
}
__device__ __forceinline__ void ldm_x4_t(uint32_t* r, uint32_t a) {
    asm volatile("ldmatrix.sync.aligned.m8n8.x4.trans.shared.b16 {%0,%1,%2,%3}, [%4];\n"
                 : "=r"(r[0]), "=r"(r[1]), "=r"(r[2]), "=r"(r[3]) : "r"(a));
}
__device__ __forceinline__ void mma_h(float* d, const uint32_t* a,
                                      uint32_t b0, uint32_t b1) {
    asm volatile("mma.sync.aligned.m16n8k16.row.col.f32.f16.f16.f32 "
                 "{%0,%1,%2,%3}, {%4,%5,%6,%7}, {%8,%9}, {%0,%1,%2,%3};\n"
                 : "+f"(d[0]), "+f"(d[1]), "+f"(d[2]), "+f"(d[3])
                 : "r"(a[0]), "r"(a[1]), "r"(a[2]), "r"(a[3]), "r"(b0), "r"(b1));
}
__device__ __forceinline__ uint32_t packh2(float x, float y) {
    __half2 h = __floats2half2_rn(x, y);
    return *(uint32_t*)&h;
}

// ---------------------------------------------------------------------------
// fp32 -> fp16, vectorized x4
// ---------------------------------------------------------------------------
__global__ void cvt_h4(const float4* __restrict__ in, __half2* __restrict__ out, int n4)
{
    int i = blockIdx.x * blockDim.x + threadIdx.x;
    if (i >= n4) return;
    float4 x = in[i];
    out[2 * i + 0] = __floats2half2_rn(x.x, x.y);
    out[2 * i + 1] = __floats2half2_rn(x.z, x.w);
}

// ---------------------------------------------------------------------------
// Single-term fp16 HMMA GEMM core: C[M,N] = A[M,K] @ B[N,K]^T
// BM=BN=128, BK=32, 2-stage cp.async, 2 smem tiles/stage (A, B), 8 warps.
// ---------------------------------------------------------------------------
#define SSTRIDE 40
#define TILE_B (128 * SSTRIDE * 2)   // 10240 B
#define STAGE_B (2 * TILE_B)         // 20480 B
#define GEMM_SMEM (2 * STAGE_B)      // 40960 B
#define KT32 (DIMN / 32)             // 32

__device__ __forceinline__ void gemm_core(
    const __half* pA, const __half* pB,
    uint32_t dst0, uint32_t aoff, uint32_t boff,
    float acc[2][8][4])
{
#define PREF(kt, st) do {                                                   \
        uint32_t db = dst0 + (uint32_t)(st) * STAGE_B;                      \
        const __half* s0 = pA + (kt) * 32;                                  \
        const __half* s1 = pB + (kt) * 32;                                  \
        cp16(db,          s0); cp16(db + 16,          s0 + 8);              \
        cp16(db + TILE_B, s1); cp16(db + TILE_B + 16, s1 + 8);              \
        cp_commit();                                                        \
    } while (0)

    PREF(0, 0);
    for (int kt = 0; kt < KT32; kt++) {
        const int st = kt & 1;
        if (kt + 1 < KT32) { PREF(kt + 1, st ^ 1); cpwait<1>(); }
        else               { cpwait<0>(); }
        __syncthreads();

        const uint32_t sb = (uint32_t)st * STAGE_B;
#pragma unroll
        for (int kk = 0; kk < 2; kk++) {
            const uint32_t ko = sb + kk * 32;
            uint32_t a[2][4], b[8][2];
            ldm_x4(a[0], aoff + ko);
            ldm_x4(a[1], aoff + ko + 16 * SSTRIDE * 2);
#pragma unroll
            for (int ng = 0; ng < 4; ng++) {
                uint32_t r[4];
                ldm_x4(r, boff + ko + ng * 16 * SSTRIDE * 2);
                b[2 * ng][0] = r[0]; b[2 * ng][1] = r[2];
                b[2 * ng + 1][0] = r[1]; b[2 * ng + 1][1] = r[3];
            }
#pragma unroll
            for (int mt = 0; mt < 2; mt++)
#pragma unroll
                for (int nt = 0; nt < 8; nt++)
                    mma_h(acc[mt][nt], a[mt], b[nt][0], b[nt][1]);
        }
        __syncthreads();
    }
#undef PREF
}

// fused QKV: z selects weight + fp16 output
__global__ __launch_bounds__(256, 1)
void gemm_qkv(const __half* __restrict__ A,
              const __half* __restrict__ W0, const __half* __restrict__ W1,
              const __half* __restrict__ W2,
              __half* __restrict__ O0, __half* __restrict__ O1,
              __half* __restrict__ O2)
{
    extern __shared__ __half smemh[];
    const uint32_t smem = smem_u32(smemh);
    const int tid = threadIdx.x, lane = tid & 31, w = tid >> 5;
    const int m0 = blockIdx.y * 128, n0 = blockIdx.x * 128;
    const __half* Bm = (blockIdx.z == 0) ? W0 : (blockIdx.z == 1 ? W1 : W2);
    __half* C = (blockIdx.z == 0) ? O0 : (blockIdx.z == 1 ? O1 : O2);

    const int lr = tid & 127, lc = (tid >> 7) * 16;
    const __half* pA = A  + (size_t)(m0 + lr) * DIMN + lc;
    const __half* pB = Bm + (size_t)(n0 + lr) * DIMN + lc;
    const uint32_t dst0 = smem + (uint32_t)(lr * SSTRIDE + lc) * 2;

    const int wm = w & 3, wn = w >> 2;
    const uint32_t aoff = smem +
        (uint32_t)((wm * 32 + (lane & 15)) * SSTRIDE + (lane >> 4) * 8) * 2;
    const uint32_t boff = smem + TILE_B +
        (uint32_t)((wn * 64 + (lane & 15)) * SSTRIDE + (lane >> 4) * 8) * 2;

    float acc[2][8][4];
#pragma unroll
    for (int i = 0; i < 2; i++)
#pragma unroll
        for (int j = 0; j < 8; j++)
#pragma unroll
            for (int t = 0; t < 4; t++) acc[i][j][t] = 0.f;

    gemm_core(pA, pB, dst0, aoff, boff, acc);

    const int gr = lane >> 2, gc = (lane & 3) * 2;
#pragma unroll
    for (int mt = 0; mt < 2; mt++) {
        const int row = m0 + wm * 32 + mt * 16 + gr;
#pragma unroll
        for (int nt = 0; nt < 8; nt++) {
            const int col = n0 + wn * 64 + nt * 8 + gc;
            *(__half2*)(C + (size_t)row * DIMN + col) =
                __floats2half2_rn(acc[mt][nt][0], acc[mt][nt][1]);
            *(__half2*)(C + (size_t)(row + 8) * DIMN + col) =
                __floats2half2_rn(acc[mt][nt][2], acc[mt][nt][3]);
        }
    }
}

// final GEMM: fp32 out + bias
__global__ __launch_bounds__(256, 1)
void gemm_out(const __half* __restrict__ A, const __half* __restrict__ Bm,
              const float* __restrict__ bias, float* __restrict__ C)
{
    extern __shared__ __half smemh[];
    const uint32_t smem = smem_u32(smemh);
    const int tid = threadIdx.x, lane = tid & 31, w = tid >> 5;
    const int m0 = blockIdx.y * 128, n0 = blockIdx.x * 128;

    const int lr = tid & 127, lc = (tid >> 7) * 16;
    const __half* pA = A  + (size_t)(m0 + lr) * DIMN + lc;
    const __half* pB = Bm + (size_t)(n0 + lr) * DIMN + lc;
    const uint32_t dst0 = smem + (uint32_t)(lr * SSTRIDE + lc) * 2;

    const int wm = w & 3, wn = w >> 2;
    const uint32_t aoff = smem +
        (uint32_t)((wm * 32 + (lane & 15)) * SSTRIDE + (lane >> 4) * 8) * 2;
    const uint32_t boff = smem + TILE_B +
        (uint32_t)((wn * 64 + (lane & 15)) * SSTRIDE + (lane >> 4) * 8) * 2;

    float acc[2][8][4];
#pragma unroll
    for (int i = 0; i < 2; i++)
#pragma unroll
        for (int j = 0; j < 8; j++)
#pragma unroll
            for (int t = 0; t < 4; t++) acc[i][j][t] = 0.f;

    gemm_core(pA, pB, dst0, aoff, boff, acc);

    const int gr = lane >> 2, gc = (lane & 3) * 2;
#pragma unroll
    for (int mt = 0; mt < 2; mt++) {
        const int row = m0 + wm * 32 + mt * 16 + gr;
#pragma unroll
        for (int nt = 0; nt < 8; nt++) {
            const int col = n0 + wn * 64 + nt * 8 + gc;
            const float b0 = bias[col], b1 = bias[col + 1];
            *(float2*)(C + (size_t)row * DIMN + col) =
                make_float2(acc[mt][nt][0] + b0, acc[mt][nt][1] + b1);
            *(float2*)(C + (size_t)(row + 8) * DIMN + col) =
                make_float2(acc[mt][nt][2] + b0, acc[mt][nt][3] + b1);
        }
    }
}

// ---------------------------------------------------------------------------
// HMMA block-local attention. One CTA per (b, blk, head), 9 warps.
// S = QK^T (fp16 mma, fp32 acc), no-max softmax, O = P·V, fp16 output
// (+ global-attention add on row 0).
// ---------------------------------------------------------------------------
#define AQS 72                              // smem row stride (halfs)
#define AT_SMEM (3 * 144 * AQS * 2)         // 62208 B

__global__ __launch_bounds__(288, 1)
void blk_attn_tc(const __half* __restrict__ q16, const __half* __restrict__ k16,
                 const __half* __restrict__ v16, const float* __restrict__ glob,
                 __half* __restrict__ a16)
{
    extern __shared__ __half sh[];
    __half* Qs = sh;
    __half* Ks = sh + 144 * AQS;
    __half* Vs = Ks + 144 * AQS;

    const int bid = blockIdx.x;
    const int h = bid & 15, blk = (bid >> 4) & 31, b = bid >> 9;
    const size_t gbase = ((size_t)(b * NLEN + blk * BLKLEN)) * DIMN + h * DK;
    const int tid = threadIdx.x, lane = tid & 31, wid = tid >> 5;

    const uint4 z4 = make_uint4(0, 0, 0, 0);
    for (int i = tid; i < 144 * 8; i += 288) {
        const int r = i >> 3, c = (i & 7) * 8;
        uint4 qv = z4, kv = z4, vv = z4;
        if (r < BLKLEN) {
            const size_t g = gbase + (size_t)r * DIMN + c;
            qv = *(const uint4*)(q16 + g);
            kv = *(const uint4*)(k16 + g);
            vv = *(const uint4*)(v16 + g);
        }
        *(uint4*)&Qs[r * AQS + c] = qv;
        *(uint4*)&Ks[r * AQS + c] = kv;
        *(uint4*)&Vs[r * AQS + c] = vv;
    }
    __syncthreads();

    const int m0 = wid * 16;          // 9 warps -> 9 m-tiles (rows 0..143)
    const int cbase = (lane & 3) * 2;
    const int gr = lane >> 2;

    uint32_t aq[4][4];
#pragma unroll
    for (int ks = 0; ks < 4; ks++) {
        uint32_t ad = smem_u32(&Qs[(m0 + (lane & 15)) * AQS + ks * 16 + (lane >> 4) * 8]);
        ldm_x4(aq[ks], ad);
    }

    float sacc[17][4];
#pragma unroll
    for (int j = 0; j < 17; j++)
#pragma unroll
        for (int t = 0; t < 4; t++) sacc[j][t] = 0.f;

#pragma unroll
    for (int ks = 0; ks < 4; ks++) {
#pragma unroll
        for (int jp = 0; jp < 8; jp++) {
            uint32_t r[4];
            uint32_t ad = smem_u32(&Ks[(jp * 16 + (lane & 15)) * AQS
                                       + ks * 16 + (lane >> 4) * 8]);
            ldm_x4(r, ad);
            mma_h(sacc[2 * jp],     aq[ks], r[0], r[2]);
            mma_h(sacc[2 * jp + 1], aq[ks], r[1], r[3]);
        }
        {
            uint32_t r[4];
            uint32_t ad = smem_u32(&Ks[(128 + (lane & 15)) * AQS
                                       + ks * 16 + (lane >> 4) * 8]);
            ldm_x4(r, ad);
            mma_h(sacc[16], aq[ks], r[0], r[2]);
        }
    }

    const float scale = 0.125f;
    float l0 = 0.f, l1 = 0.f;
#pragma unroll
    for (int j = 0; j < 17; j++) {
        const int c0 = j * 8 + cbase;
        const bool v0 = c0 < BLKLEN, v1 = (c0 + 1) < BLKLEN;
        float p0 = v0 ? __expf(sacc[j][0] * scale) : 0.f;
        float p1 = v1 ? __expf(sacc[j][1] * scale) : 0.f;
        float p2 = v0 ? __expf(sacc[j][2] * scale) : 0.f;
        float p3 = v1 ? __expf(sacc[j][3] * scale) : 0.f;
        sacc[j][0] = p0; sacc[j][1] = p1; sacc[j][2] = p2; sacc[j][3] = p3;
        l0 += p0 + p1; l1 += p2 + p3;
    }
    l0 += __shfl_xor_sync(0xFFFFFFFFu, l0, 1);
    l0 += __shfl_xor_sync(0xFFFFFFFFu, l0, 2);
    l1 += __shfl_xor_sync(0xFFFFFFFFu, l1, 1);
    l1 += __shfl_xor_sync(0xFFFFFFFFu, l1, 2);

    float oacc[8][4];
#pragma unroll
    for (int g = 0; g < 8; g++)
#pragma unroll
        for (int t = 0; t < 4; t++) oacc[g][t] = 0.f;

    const int vmat = lane >> 3;
#pragma unroll
    for (int kp = 0; kp < 9; kp++) {
        uint32_t pa[4];
        const int t0 = 2 * kp, t1 = 2 * kp + 1;
        pa[0] = packh2(sacc[t0][0], sacc[t0][1]);
        pa[1] = packh2(sacc[t0][2], sacc[t0][3]);
        if (t1 < 17) {
            pa[2] = packh2(sacc[t1][0], sacc[t1][1]);
            pa[3] = packh2(sacc[t1][2], sacc[t1][3]);
        } else { pa[2] = 0u; pa[3] = 0u; }
#pragma unroll
        for (int g = 0; g < 4; g++) {
            uint32_t r[4];
            uint32_t ad = smem_u32(&Vs[(kp * 16 + (vmat & 1) * 8 + (lane & 7)) * AQS
                                       + g * 16 + (vmat >> 1) * 8]);
            ldm_x4_t(r, ad);
            mma_h(oacc[2 * g],     pa, r[0], r[1]);
            mma_h(oacc[2 * g + 1], pa, r[2], r[3]);
        }
    }

    const float rl0 = 1.0f / l0, rl1 = 1.0f / l1;
    const int r0 = m0 + gr, r1 = r0 + 8;
    const float* gp = glob + (((size_t)(b * NB + blk) * HEADS) + h) * DK;
#pragma unroll
    for (int g = 0; g < 8; g++) {
        const int col = g * 8 + cbase;
        float o0 = oacc[g][0] * rl0, o1 = oacc[g][1] * rl0;
        float o2 = oacc[g][2] * rl1, o3 = oacc[g][3] * rl1;
        if (r0 == 0) { o0 += gp[col]; o1 += gp[col + 1]; }
        if (r0 < BLKLEN)
            *(__half2*)(a16 + gbase + (size_t)r0 * DIMN + col) =
                __floats2half2_rn(o0, o1);
        if (r1 < BLKLEN)
            *(__half2*)(a16 + gbase + (size_t)r1 * DIMN + col) =
                __floats2half2_rn(o2, o3);
    }
}

// ---------------------------------------------------------------------------
// Global attention over first tokens (fp16 in, fp32 out to g_glob)
// ---------------------------------------------------------------------------
__global__ __launch_bounds__(32)
void glob_attn_h(const __half* __restrict__ q16, const __half* __restrict__ k16,
                 const __half* __restrict__ v16, float* __restrict__ glob)
{
    __shared__ float ks[NB * DK];
    __shared__ float vs[NB * DK];
    const int b = blockIdx.x >> 4;
    const int h = blockIdx.x & 15;
    const int tid = threadIdx.x;

    const size_t rowbase = ((size_t)(b * NLEN + tid * BLKLEN)) * DIMN + h * DK;
#pragma unroll
    for (int i = 0; i < DK / 2; i++) {
        float2 kf = __half22float2(*(const __half2*)(k16 + rowbase + 2 * i));
        float2 vf = __half22float2(*(const __half2*)(v16 + rowbase + 2 * i));
        ks[tid * DK + 2 * i] = kf.x; ks[tid * DK + 2 * i + 1] = kf.y;
        vs[tid * DK + 2 * i] = vf.x; vs[tid * DK + 2 * i + 1] = vf.y;
    }
    __syncthreads();

    float qr[DK];
#pragma unroll
    for (int i = 0; i < DK / 2; i++) {
        float2 f = __half22float2(*(const __half2*)(q16 + rowbase + 2 * i));
        qr[2 * i] = f.x; qr[2 * i + 1] = f.y;
    }
    float acc[DK];
#pragma unroll
    for (int d = 0; d < DK; d++) acc[d] = 0.f;
    float l = 0.f;
    const float scale = 0.125f;

    for (int key = 0; key < NB; key++) {
        const float* kp = ks + key * DK;
        float s = 0.f;
#pragma unroll
        for (int i = 0; i < DK; i++) s += qr[i] * kp[i];
        const float p = __expf(s * scale);
        l += p;
        const float* vp = vs + key * DK;
#pragma unroll
        for (int i = 0; i < DK; i++) acc[i] += p * vp[i];
    }

    const float rl = 1.0f / l;
    float* op = glob + (((size_t)(b * NB + tid) * HEADS) + h) * DK;
#pragma unroll
    for (int i = 0; i < DK; i++) op[i] = acc[i] * rl;
}

// ---------------------------------------------------------------------------
extern "C" void kernel_launch(void* const* d_in, const int* in_sizes, int n_in,
                              void* d_out, int out_size)
{
    const float* x  = (const float*)d_in[0];
    const float* Wq = (const float*)d_in[1];
    const float* Wk = (const float*)d_in[2];
    const float* Wv = (const float*)d_in[3];
    const float* Wo = (const float*)d_in[4];
    const float* bo = (const float*)d_in[5];
    float* out = (float*)d_out;

    __half *x16, *q16, *k16, *v16, *a16, *w16;
    float* glob;
    cudaGetSymbolAddress((void**)&x16, g_x16);
    cudaGetSymbolAddress((void**)&q16, g_q16);
    cudaGetSymbolAddress((void**)&k16, g_k16);
    cudaGetSymbolAddress((void**)&v16, g_v16);
    cudaGetSymbolAddress((void**)&a16, g_a16);
    cudaGetSymbolAddress((void**)&w16, g_w16);
    cudaGetSymbolAddress((void**)&glob, g_glob);

    cudaFuncSetAttribute(gemm_qkv, cudaFuncAttributeMaxDynamicSharedMemorySize, GEMM_SMEM);
    cudaFuncSetAttribute(gemm_out, cudaFuncAttributeMaxDynamicSharedMemorySize, GEMM_SMEM);
    cudaFuncSetAttribute(blk_attn_tc, cudaFuncAttributeMaxDynamicSharedMemorySize, AT_SMEM);

    const int W = DIMN * DIMN;
    const int n4x = TOK * DIMN / 4;
    const int n4w = W / 4;

    cvt_h4<<<(n4x + 255) / 256, 256>>>((const float4*)x,  (__half2*)x16, n4x);
    cvt_h4<<<(n4w + 255) / 256, 256>>>((const float4*)Wq, (__half2*)(w16 + 0 * W), n4w);
    cvt_h4<<<(n4w + 255) / 256, 256>>>((const float4*)Wk, (__half2*)(w16 + 1 * W), n4w);
    cvt_h4<<<(n4w + 255) / 256, 256>>>((const float4*)Wv, (__half2*)(w16 + 2 * W), n4w);
    cvt_h4<<<(n4w + 255) / 256, 256>>>((const float4*)Wo, (__half2*)(w16 + 3 * W), n4w);

    dim3 gQKV(DIMN / 128, TOK / 128, 3);   // (8, 129, 3)
    gemm_qkv<<<gQKV, 256, GEMM_SMEM>>>(x16,
        w16 + 0 * W, w16 + 1 * W, w16 + 2 * W, q16, k16, v16);

    glob_attn_h<<<B_SZ * HEADS, 32>>>(q16, k16, v16, glob);

    blk_attn_tc<<<B_SZ * NB * HEADS, 288, AT_SMEM>>>(q16, k16, v16, glob, a16);

    dim3 gO(DIMN / 128, TOK / 128);        // (8, 129)
    gemm_out<<<gO, 256, GEMM_SMEM>>>(a16, w16 + 3 * W, bo, out);
}

// round 7
// speedup vs baseline: 23.2710x; 1.0756x over previous
#include <cuda_runtime.h>
#include <cuda_fp16.h>
#include <cstdint>
#include <math.h>

#define B_SZ   4
#define NLEN   4128
#define DIMN   1024
#define HEADS  16
#define BLKLEN 129
#define NB     32
#define DK     64
#define TOK    (B_SZ * NLEN)   // 16512

// ---------------- scratch (device globals: allocation-free) ----------------
__device__ __half g_x16[TOK * DIMN];
__device__ __half g_q16[TOK * DIMN];
__device__ __half g_k16[TOK * DIMN];
__device__ __half g_v16[TOK * DIMN];
__device__ __half g_a16[TOK * DIMN];
__device__ __half g_w16[4 * DIMN * DIMN];
__device__ float  g_glob[B_SZ * NB * HEADS * DK];

// ============================ helpers ======================================
__device__ __forceinline__ uint32_t smem_u32(const void* p) {
    return (uint32_t)__cvta_generic_to_shared(p);
}
__device__ __forceinline__ void cp16(uint32_t d, const void* s) {
    asm volatile("cp.async.cg.shared.global [%0], [%1], 16;\n" :: "r"(d), "l"(s));
}
__device__ __forceinline__ void cp_commit() {
    asm volatile("cp.async.commit_group;\n");
}
template<int N_> __device__ __forceinline__ void cpwait() {
    asm volatile("cp.async.wait_group %0;\n" :: "n"(N_));
}
__device__ __forceinline__ void ldm_x4(uint32_t* r, uint32_t a) {
    asm volatile("ldmatrix.sync.aligned.m8n8.x4.shared.b16 {%0,%1,%2,%3}, [%4];\n"
                 : "=r"(r[0]), "=r"(r[1]), "=r"(r[2]), "=r"(r[3]) : "r"(a));
}
__device__ __forceinline__ void ldm_x4_t(uint32_t* r, uint32_t a) {
    asm volatile("ldmatrix.sync.aligned.m8n8.x4.trans.shared.b16 {%0,%1,%2,%3}, [%4];\n"
                 : "=r"(r[0]), "=r"(r[1]), "=r"(r[2]), "=r"(r[3]) : "r"(a));
}
__device__ __forceinline__ void mma_h(float* d, const uint32_t* a,
                                      uint32_t b0, uint32_t b1) {
    asm volatile("mma.sync.aligned.m16n8k16.row.col.f32.f16.f16.f32 "
                 "{%0,%1,%2,%3}, {%4,%5,%6,%7}, {%8,%9}, {%0,%1,%2,%3};\n"
                 : "+f"(d[0]), "+f"(d[1]), "+f"(d[2]), "+f"(d[3])
                 : "r"(a[0]), "r"(a[1]), "r"(a[2]), "r"(a[3]), "r"(b0), "r"(b1));
}
__device__ __forceinline__ uint32_t packh2(float x, float y) {
    __half2 h = __floats2half2_rn(x, y);
    return *(uint32_t*)&h;
}

// ---------------------------------------------------------------------------
// conversions (x separate; all 4 weights in one launch via blockIdx.y)
// ---------------------------------------------------------------------------
__global__ void cvt_h4(const float4* __restrict__ in, __half2* __restrict__ out, int n4)
{
    int i = blockIdx.x * blockDim.x + threadIdx.x;
    if (i >= n4) return;
    float4 x = in[i];
    out[2 * i + 0] = __floats2half2_rn(x.x, x.y);
    out[2 * i + 1] = __floats2half2_rn(x.z, x.w);
}

__global__ void cvt_w4(const float4* __restrict__ W0, const float4* __restrict__ W1,
                       const float4* __restrict__ W2, const float4* __restrict__ W3,
                       __half2* __restrict__ out, int n4)
{
    const int z = blockIdx.y;
    const float4* src = (z == 0) ? W0 : (z == 1) ? W1 : (z == 2) ? W2 : W3;
    __half2* dst = out + (size_t)z * (DIMN * DIMN / 2);
    int i = blockIdx.x * blockDim.x + threadIdx.x;
    if (i >= n4) return;
    float4 x = src[i];
    dst[2 * i + 0] = __floats2half2_rn(x.x, x.y);
    dst[2 * i + 1] = __floats2half2_rn(x.z, x.w);
}

// ---------------------------------------------------------------------------
// Single-term fp16 HMMA GEMM core: C[M,N] = A[M,K] @ B[N,K]^T
// BM=BN=128, BK=32, 2-stage cp.async, 8 warps, 2 CTAs/SM.
// ---------------------------------------------------------------------------
#define SSTRIDE 40
#define TILE_B (128 * SSTRIDE * 2)   // 10240 B
#define STAGE_B (2 * TILE_B)         // 20480 B
#define GEMM_SMEM (2 * STAGE_B)      // 40960 B
#define KT32 (DIMN / 32)             // 32

__device__ __forceinline__ void gemm_core(
    const __half* pA, const __half* pB,
    uint32_t dst0, uint32_t aoff, uint32_t boff,
    float acc[2][8][4])
{
#define PREF(kt, st) do {                                                   \
        uint32_t db = dst0 + (uint32_t)(st) * STAGE_B;                      \
        const __half* s0 = pA + (kt) * 32;                                  \
        const __half* s1 = pB + (kt) * 32;                                  \
        cp16(db,          s0); cp16(db + 16,          s0 + 8);              \
        cp16(db + TILE_B, s1); cp16(db + TILE_B + 16, s1 + 8);              \
        cp_commit();                                                        \
    } while (0)

    PREF(0, 0);
    for (int kt = 0; kt < KT32; kt++) {
        const int st = kt & 1;
        if (kt + 1 < KT32) { PREF(kt + 1, st ^ 1); cpwait<1>(); }
        else               { cpwait<0>(); }
        __syncthreads();

        const uint32_t sb = (uint32_t)st * STAGE_B;
#pragma unroll
        for (int kk = 0; kk < 2; kk++) {
            const uint32_t ko = sb + kk * 32;
            uint32_t a[2][4], b[8][2];
            ldm_x4(a[0], aoff + ko);
            ldm_x4(a[1], aoff + ko + 16 * SSTRIDE * 2);
#pragma unroll
            for (int ng = 0; ng < 4; ng++) {
                uint32_t r[4];
                ldm_x4(r, boff + ko + ng * 16 * SSTRIDE * 2);
                b[2 * ng][0] = r[0]; b[2 * ng][1] = r[2];
                b[2 * ng + 1][0] = r[1]; b[2 * ng + 1][1] = r[3];
            }
#pragma unroll
            for (int mt = 0; mt < 2; mt++)
#pragma unroll
                for (int nt = 0; nt < 8; nt++)
                    mma_h(acc[mt][nt], a[mt], b[nt][0], b[nt][1]);
        }
        __syncthreads();
    }
#undef PREF
}

// fused QKV: z selects weight + fp16 output
__global__ __launch_bounds__(256, 2)
void gemm_qkv(const __half* __restrict__ A,
              const __half* __restrict__ W0, const __half* __restrict__ W1,
              const __half* __restrict__ W2,
              __half* __restrict__ O0, __half* __restrict__ O1,
              __half* __restrict__ O2)
{
    extern __shared__ __half smemh[];
    const uint32_t smem = smem_u32(smemh);
    const int tid = threadIdx.x, lane = tid & 31, w = tid >> 5;
    const int m0 = blockIdx.y * 128, n0 = blockIdx.x * 128;
    const __half* Bm = (blockIdx.z == 0) ? W0 : (blockIdx.z == 1 ? W1 : W2);
    __half* C = (blockIdx.z == 0) ? O0 : (blockIdx.z == 1 ? O1 : O2);

    const int lr = tid & 127, lc = (tid >> 7) * 16;
    const __half* pA = A  + (size_t)(m0 + lr) * DIMN + lc;
    const __half* pB = Bm + (size_t)(n0 + lr) * DIMN + lc;
    const uint32_t dst0 = smem + (uint32_t)(lr * SSTRIDE + lc) * 2;

    const int wm = w & 3, wn = w >> 2;
    const uint32_t aoff = smem +
        (uint32_t)((wm * 32 + (lane & 15)) * SSTRIDE + (lane >> 4) * 8) * 2;
    const uint32_t boff = smem + TILE_B +
        (uint32_t)((wn * 64 + (lane & 15)) * SSTRIDE + (lane >> 4) * 8) * 2;

    float acc[2][8][4];
#pragma unroll
    for (int i = 0; i < 2; i++)
#pragma unroll
        for (int j = 0; j < 8; j++)
#pragma unroll
            for (int t = 0; t < 4; t++) acc[i][j][t] = 0.f;

    gemm_core(pA, pB, dst0, aoff, boff, acc);

    const int gr = lane >> 2, gc = (lane & 3) * 2;
#pragma unroll
    for (int mt = 0; mt < 2; mt++) {
        const int row = m0 + wm * 32 + mt * 16 + gr;
#pragma unroll
        for (int nt = 0; nt < 8; nt++) {
            const int col = n0 + wn * 64 + nt * 8 + gc;
            *(__half2*)(C + (size_t)row * DIMN + col) =
                __floats2half2_rn(acc[mt][nt][0], acc[mt][nt][1]);
            *(__half2*)(C + (size_t)(row + 8) * DIMN + col) =
                __floats2half2_rn(acc[mt][nt][2], acc[mt][nt][3]);
        }
    }
}

// final GEMM: fp32 out + bias
__global__ __launch_bounds__(256, 2)
void gemm_out(const __half* __restrict__ A, const __half* __restrict__ Bm,
              const float* __restrict__ bias, float* __restrict__ C)
{
    extern __shared__ __half smemh[];
    const uint32_t smem = smem_u32(smemh);
    const int tid = threadIdx.x, lane = tid & 31, w = tid >> 5;
    const int m0 = blockIdx.y * 128, n0 = blockIdx.x * 128;

    const int lr = tid & 127, lc = (tid >> 7) * 16;
    const __half* pA = A  + (size_t)(m0 + lr) * DIMN + lc;
    const __half* pB = Bm + (size_t)(n0 + lr) * DIMN + lc;
    const uint32_t dst0 = smem + (uint32_t)(lr * SSTRIDE + lc) * 2;

    const int wm = w & 3, wn = w >> 2;
    const uint32_t aoff = smem +
        (uint32_t)((wm * 32 + (lane & 15)) * SSTRIDE + (lane >> 4) * 8) * 2;
    const uint32_t boff = smem + TILE_B +
        (uint32_t)((wn * 64 + (lane & 15)) * SSTRIDE + (lane >> 4) * 8) * 2;

    float acc[2][8][4];
#pragma unroll
    for (int i = 0; i < 2; i++)
#pragma unroll
        for (int j = 0; j < 8; j++)
#pragma unroll
            for (int t = 0; t < 4; t++) acc[i][j][t] = 0.f;

    gemm_core(pA, pB, dst0, aoff, boff, acc);

    const int gr = lane >> 2, gc = (lane & 3) * 2;
#pragma unroll
    for (int mt = 0; mt < 2; mt++) {
        const int row = m0 + wm * 32 + mt * 16 + gr;
#pragma unroll
        for (int nt = 0; nt < 8; nt++) {
            const int col = n0 + wn * 64 + nt * 8 + gc;
            const float b0 = bias[col], b1 = bias[col + 1];
            *(float2*)(C + (size_t)row * DIMN + col) =
                make_float2(acc[mt][nt][0] + b0, acc[mt][nt][1] + b1);
            *(float2*)(C + (size_t)(row + 8) * DIMN + col) =
                make_float2(acc[mt][nt][2] + b0, acc[mt][nt][3] + b1);
        }
    }
}

// ---------------------------------------------------------------------------
// HMMA block-local attention, register-lean (target 2 CTAs/SM).
// One CTA per (b, blk, head), 9 warps x 16 query rows.
// S-phase: jp outer / ks inner, 8 fp32 accs live; P packed to fp16 on the fly.
// ---------------------------------------------------------------------------
#define AQS 72                              // smem row stride (halfs)
#define AT_SMEM (3 * 144 * AQS * 2)         // 62208 B

__global__ __launch_bounds__(288, 2)
void blk_attn_tc(const __half* __restrict__ q16, const __half* __restrict__ k16,
                 const __half* __restrict__ v16, const float* __restrict__ glob,
                 __half* __restrict__ a16)
{
    extern __shared__ __half sh[];
    __half* Qs = sh;
    __half* Ks = sh + 144 * AQS;
    __half* Vs = Ks + 144 * AQS;

    const int bid = blockIdx.x;
    const int h = bid & 15, blk = (bid >> 4) & 31, b = bid >> 9;
    const size_t gbase = ((size_t)(b * NLEN + blk * BLKLEN)) * DIMN + h * DK;
    const int tid = threadIdx.x, lane = tid & 31, wid = tid >> 5;

    // cp.async load of Q/K/V tiles; zero-fill pad rows (129..143)
    const uint4 z4 = make_uint4(0, 0, 0, 0);
#pragma unroll
    for (int j = 0; j < 4; j++) {
        const int i = tid + j * 288;
        const int r = i >> 3, c = (i & 7) * 8;
        const uint32_t so = (uint32_t)(r * AQS + c) * 2;
        if (r < BLKLEN) {
            const size_t g = gbase + (size_t)r * DIMN + c;
            cp16(smem_u32(Qs) + so, q16 + g);
            cp16(smem_u32(Ks) + so, k16 + g);
            cp16(smem_u32(Vs) + so, v16 + g);
        } else {
            *(uint4*)&Qs[r * AQS + c] = z4;
            *(uint4*)&Ks[r * AQS + c] = z4;
            *(uint4*)&Vs[r * AQS + c] = z4;
        }
    }
    cp_commit();
    cpwait<0>();
    __syncthreads();

    const int m0 = wid * 16;
    const int cbase = (lane & 3) * 2;
    const int gr = lane >> 2;
    const uint32_t loff = (uint32_t)((lane & 15) * AQS + (lane >> 4) * 8) * 2;

    // Q fragments for the 4 k-steps of DK=64
    uint32_t aq[4][4];
    {
        const uint32_t qb = smem_u32(Qs) + (uint32_t)(m0 * AQS) * 2 + loff;
#pragma unroll
        for (int ks = 0; ks < 4; ks++) ldm_x4(aq[ks], qb + ks * 32);
    }

    // S = QK^T, exp, pack to fp16 P on the fly. P2[j][0]=rows gr, [1]=rows gr+8.
    const float scale = 0.125f;
    uint32_t P2[17][2];
    float l0 = 0.f, l1 = 0.f;
    const uint32_t kb = smem_u32(Ks) + loff;
#pragma unroll
    for (int jp = 0; jp < 8; jp++) {
        float e0[4] = {0.f, 0.f, 0.f, 0.f};
        float e1[4] = {0.f, 0.f, 0.f, 0.f};
        const uint32_t kjb = kb + (uint32_t)(jp * 16 * AQS) * 2;
#pragma unroll
        for (int ks = 0; ks < 4; ks++) {
            uint32_t r[4];
            ldm_x4(r, kjb + ks * 32);
            mma_h(e0, aq[ks], r[0], r[2]);
            mma_h(e1, aq[ks], r[1], r[3]);
        }
        // cols of tiles 2jp (<=127) and 2jp+1 (<=127): all valid
        float p00 = __expf(e0[0] * scale), p01 = __expf(e0[1] * scale);
        float p02 = __expf(e0[2] * scale), p03 = __expf(e0[3] * scale);
        float p10 = __expf(e1[0] * scale), p11 = __expf(e1[1] * scale);
        float p12 = __expf(e1[2] * scale), p13 = __expf(e1[3] * scale);
        l0 += (p00 + p01) + (p10 + p11);
        l1 += (p02 + p03) + (p12 + p13);
        P2[2 * jp][0] = packh2(p00, p01);
        P2[2 * jp][1] = packh2(p02, p03);
        P2[2 * jp + 1][0] = packh2(p10, p11);
        P2[2 * jp + 1][1] = packh2(p12, p13);
    }
    {   // tile 16: keys 128..135, only col 128 valid (cbase==0, first elem)
        float e0[4] = {0.f, 0.f, 0.f, 0.f};
        const uint32_t kjb = kb + (uint32_t)(128 * AQS) * 2;
#pragma unroll
        for (int ks = 0; ks < 4; ks++) {
            uint32_t r[4];
            ldm_x4(r, kjb + ks * 32);
            mma_h(e0, aq[ks], r[0], r[2]);
        }
        const bool v = (cbase == 0);
        float p0 = v ? __expf(e0[0] * scale) : 0.f;
        float p2 = v ? __expf(e0[2] * scale) : 0.f;
        l0 += p0; l1 += p2;
        P2[16][0] = packh2(p0, 0.f);
        P2[16][1] = packh2(p2, 0.f);
    }
    l0 += __shfl_xor_sync(0xFFFFFFFFu, l0, 1);
    l0 += __shfl_xor_sync(0xFFFFFFFFu, l0, 2);
    l1 += __shfl_xor_sync(0xFFFFFFFFu, l1, 1);
    l1 += __shfl_xor_sync(0xFFFFFFFFu, l1, 2);

    // O = P V
    float oacc[8][4];
#pragma unroll
    for (int g = 0; g < 8; g++)
#pragma unroll
        for (int t = 0; t < 4; t++) oacc[g][t] = 0.f;

    const int vmat = lane >> 3;
    const uint32_t vb = smem_u32(Vs) +
        (uint32_t)(((vmat & 1) * 8 + (lane & 7)) * AQS + (vmat >> 1) * 8) * 2;
#pragma unroll
    for (int kp = 0; kp < 9; kp++) {
        uint32_t pa[4];
        pa[0] = P2[2 * kp][0];
        pa[1] = P2[2 * kp][1];
        if (kp < 8) { pa[2] = P2[2 * kp + 1][0]; pa[3] = P2[2 * kp + 1][1]; }
        else        { pa[2] = 0u; pa[3] = 0u; }
        const uint32_t vkb = vb + (uint32_t)(kp * 16 * AQS) * 2;
#pragma unroll
        for (int g = 0; g < 4; g++) {
            uint32_t r[4];
            ldm_x4_t(r, vkb + g * 32);
            mma_h(oacc[2 * g],     pa, r[0], r[1]);
            mma_h(oacc[2 * g + 1], pa, r[2], r[3]);
        }
    }

    // epilogue
    const float rl0 = 1.0f / l0, rl1 = 1.0f / l1;
    const int r0 = m0 + gr, r1 = r0 + 8;
    const float* gp = glob + (((size_t)(b * NB + blk) * HEADS) + h) * DK;
#pragma unroll
    for (int g = 0; g < 8; g++) {
        const int col = g * 8 + cbase;
        float o0 = oacc[g][0] * rl0, o1 = oacc[g][1] * rl0;
        float o2 = oacc[g][2] * rl1, o3 = oacc[g][3] * rl1;
        if (r0 == 0) { o0 += gp[col]; o1 += gp[col + 1]; }
        if (r0 < BLKLEN)
            *(__half2*)(a16 + gbase + (size_t)r0 * DIMN + col) =
                __floats2half2_rn(o0, o1);
        if (r1 < BLKLEN)
            *(__half2*)(a16 + gbase + (size_t)r1 * DIMN + col) =
                __floats2half2_rn(o2, o3);
    }
}

// ---------------------------------------------------------------------------
// Global attention over first tokens (fp16 in, fp32 out to g_glob)
// ---------------------------------------------------------------------------
__global__ __launch_bounds__(32)
void glob_attn_h(const __half* __restrict__ q16, const __half* __restrict__ k16,
                 const __half* __restrict__ v16, float* __restrict__ glob)
{
    __shared__ float ks[NB * DK];
    __shared__ float vs[NB * DK];
    const int b = blockIdx.x >> 4;
    const int h = blockIdx.x & 15;
    const int tid = threadIdx.x;

    const size_t rowbase = ((size_t)(b * NLEN + tid * BLKLEN)) * DIMN + h * DK;
#pragma unroll
    for (int i = 0; i < DK / 2; i++) {
        float2 kf = __half22float2(*(const __half2*)(k16 + rowbase + 2 * i));
        float2 vf = __half22float2(*(const __half2*)(v16 + rowbase + 2 * i));
        ks[tid * DK + 2 * i] = kf.x; ks[tid * DK + 2 * i + 1] = kf.y;
        vs[tid * DK + 2 * i] = vf.x; vs[tid * DK + 2 * i + 1] = vf.y;
    }
    __syncthreads();

    float qr[DK];
#pragma unroll
    for (int i = 0; i < DK / 2; i++) {
        float2 f = __half22float2(*(const __half2*)(q16 + rowbase + 2 * i));
        qr[2 * i] = f.x; qr[2 * i + 1] = f.y;
    }
    float acc[DK];
#pragma unroll
    for (int d = 0; d < DK; d++) acc[d] = 0.f;
    float l = 0.f;
    const float scale = 0.125f;

    for (int key = 0; key < NB; key++) {
        const float* kp = ks + key * DK;
        float s = 0.f;
#pragma unroll
        for (int i = 0; i < DK; i++) s += qr[i] * kp[i];
        const float p = __expf(s * scale);
        l += p;
        const float* vp = vs + key * DK;
#pragma unroll
        for (int i = 0; i < DK; i++) acc[i] += p * vp[i];
    }

    const float rl = 1.0f / l;
    float* op = glob + (((size_t)(b * NB + tid) * HEADS) + h) * DK;
#pragma unroll
    for (int i = 0; i < DK; i++) op[i] = acc[i] * rl;
}

// ---------------------------------------------------------------------------
extern "C" void kernel_launch(void* const* d_in, const int* in_sizes, int n_in,
                              void* d_out, int out_size)
{
    const float* x  = (const float*)d_in[0];
    const float* Wq = (const float*)d_in[1];
    const float* Wk = (const float*)d_in[2];
    const float* Wv = (const float*)d_in[3];
    const float* Wo = (const float*)d_in[4];
    const float* bo = (const float*)d_in[5];
    float* out = (float*)d_out;

    __half *x16, *q16, *k16, *v16, *a16, *w16;
    float* glob;
    cudaGetSymbolAddress((void**)&x16, g_x16);
    cudaGetSymbolAddress((void**)&q16, g_q16);
    cudaGetSymbolAddress((void**)&k16, g_k16);
    cudaGetSymbolAddress((void**)&v16, g_v16);
    cudaGetSymbolAddress((void**)&a16, g_a16);
    cudaGetSymbolAddress((void**)&w16, g_w16);
    cudaGetSymbolAddress((void**)&glob, g_glob);

    cudaFuncSetAttribute(gemm_qkv, cudaFuncAttributeMaxDynamicSharedMemorySize, GEMM_SMEM);
    cudaFuncSetAttribute(gemm_out, cudaFuncAttributeMaxDynamicSharedMemorySize, GEMM_SMEM);
    cudaFuncSetAttribute(blk_attn_tc, cudaFuncAttributeMaxDynamicSharedMemorySize, AT_SMEM);

    const int W = DIMN * DIMN;
    const int n4x = TOK * DIMN / 4;
    const int n4w = W / 4;

    cvt_h4<<<(n4x + 255) / 256, 256>>>((const float4*)x, (__half2*)x16, n4x);
    dim3 gW((n4w + 255) / 256, 4);
    cvt_w4<<<gW, 256>>>((const float4*)Wq, (const float4*)Wk,
                        (const float4*)Wv, (const float4*)Wo,
                        (__half2*)w16, n4w);

    dim3 gQKV(DIMN / 128, TOK / 128, 3);   // (8, 129, 3)
    gemm_qkv<<<gQKV, 256, GEMM_SMEM>>>(x16,
        w16 + 0 * W, w16 + 1 * W, w16 + 2 * W, q16, k16, v16);

    glob_attn_h<<<B_SZ * HEADS, 32>>>(q16, k16, v16, glob);

    blk_attn_tc<<<B_SZ * NB * HEADS, 288, AT_SMEM>>>(q16, k16, v16, glob, a16);

    dim3 gO(DIMN / 128, TOK / 128);        // (8, 129)
    gemm_out<<<gO, 256, GEMM_SMEM>>>(a16, w16 + 3 * W, bo, out);
}

// round 9
// speedup vs baseline: 24.9202x; 1.0709x over previous
#include <cuda_runtime.h>
#include <cuda_fp16.h>
#include <cstdint>
#include <math.h>

#define B_SZ   4
#define NLEN   4128
#define DIMN   1024
#define HEADS  16
#define BLKLEN 129
#define NB     32
#define DK     64
#define TOK    (B_SZ * NLEN)   // 16512

// ---------------- scratch (device globals: allocation-free) ----------------
__device__ __half g_x16[TOK * DIMN];
__device__ __half g_q16[TOK * DIMN];
__device__ __half g_k16[TOK * DIMN];
__device__ __half g_v16[TOK * DIMN];
__device__ __half g_a16[TOK * DIMN];
__device__ __half g_w16[4 * DIMN * DIMN];

// ============================ helpers ======================================
__device__ __forceinline__ uint32_t smem_u32(const void* p) {
    return (uint32_t)__cvta_generic_to_shared(p);
}
__device__ __forceinline__ void cp16(uint32_t d, const void* s) {
    asm volatile("cp.async.cg.shared.global [%0], [%1], 16;\n" :: "r"(d), "l"(s));
}
__device__ __forceinline__ void cp_commit() {
    asm volatile("cp.async.commit_group;\n");
}
template<int N_> __device__ __forceinline__ void cpwait() {
    asm volatile("cp.async.wait_group %0;\n" :: "n"(N_));
}
__device__ __forceinline__ void ldm_x4(uint32_t* r, uint32_t a) {
    asm volatile("ldmatrix.sync.aligned.m8n8.x4.shared.b16 {%0,%1,%2,%3}, [%4];\n"
                 : "=r"(r[0]), "=r"(r[1]), "=r"(r[2]), "=r"(r[3]) : "r"(a));
}
__device__ __forceinline__ void ldm_x4_t(uint32_t* r, uint32_t a) {
    asm volatile("ldmatrix.sync.aligned.m8n8.x4.trans.shared.b16 {%0,%1,%2,%3}, [%4];\n"
                 : "=r"(r[0]), "=r"(r[1]), "=r"(r[2]), "=r"(r[3]) : "r"(a));
}
__device__ __forceinline__ void mma_h(float* d, const uint32_t* a,
                                      uint32_t b0, uint32_t b1) {
    asm volatile("mma.sync.aligned.m16n8k16.row.col.f32.f16.f16.f32 "
                 "{%0,%1,%2,%3}, {%4,%5,%6,%7}, {%8,%9}, {%0,%1,%2,%3};\n"
                 : "+f"(d[0]), "+f"(d[1]), "+f"(d[2]), "+f"(d[3])
                 : "r"(a[0]), "r"(a[1]), "r"(a[2]), "r"(a[3]), "r"(b0), "r"(b1));
}
__device__ __forceinline__ uint32_t packh2(float x, float y) {
    __half2 h = __floats2half2_rn(x, y);
    return *(uint32_t*)&h;
}

// ---------------------------------------------------------------------------
// conversions
// ---------------------------------------------------------------------------
__global__ void cvt_h4(const float4* __restrict__ in, __half2* __restrict__ out, int n4)
{
    int i = blockIdx.x * blockDim.x + threadIdx.x;
    if (i >= n4) return;
    float4 x = in[i];
    out[2 * i + 0] = __floats2half2_rn(x.x, x.y);
    out[2 * i + 1] = __floats2half2_rn(x.z, x.w);
}

__global__ void cvt_w4(const float4* __restrict__ W0, const float4* __restrict__ W1,
                       const float4* __restrict__ W2, const float4* __restrict__ W3,
                       __half2* __restrict__ out, int n4)
{
    const int z = blockIdx.y;
    const float4* src = (z == 0) ? W0 : (z == 1) ? W1 : (z == 2) ? W2 : W3;
    __half2* dst = out + (size_t)z * (DIMN * DIMN / 2);
    int i = blockIdx.x * blockDim.x + threadIdx.x;
    if (i >= n4) return;
    float4 x = src[i];
    dst[2 * i + 0] = __floats2half2_rn(x.x, x.y);
    dst[2 * i + 1] = __floats2half2_rn(x.z, x.w);
}

// ---------------------------------------------------------------------------
// Single-term fp16 HMMA GEMM core: C[M,N] = A[M,K] @ B[N,K]^T
// BM=BN=128, BK=32, 3-stage cp.async, 8 warps, 2 CTAs/SM.
// ---------------------------------------------------------------------------
#define SSTRIDE 40
#define TILE_B (128 * SSTRIDE * 2)   // 10240 B
#define STAGE_B (2 * TILE_B)         // 20480 B
#define GEMM_SMEM (3 * STAGE_B)      // 61440 B
#define KT32 (DIMN / 32)             // 32

__device__ __forceinline__ void gemm_core(
    const __half* pA, const __half* pB,
    uint32_t dst0, uint32_t aoff, uint32_t boff,
    float acc[2][8][4])
{
#define PREF(kt, st) do {                                                   \
        uint32_t db = dst0 + (uint32_t)(st) * STAGE_B;                      \
        const __half* s0 = pA + (kt) * 32;                                  \
        const __half* s1 = pB + (kt) * 32;                                  \
        cp16(db,          s0); cp16(db + 16,          s0 + 8);              \
        cp16(db + TILE_B, s1); cp16(db + TILE_B + 16, s1 + 8);              \
        cp_commit();                                                        \
    } while (0)

    PREF(0, 0);
    PREF(1, 1);
    for (int kt = 0; kt < KT32; kt++) {
        const int st = kt % 3;
        if (kt + 2 < KT32)      { PREF(kt + 2, (kt + 2) % 3); cpwait<2>(); }
        else if (kt + 1 < KT32) { cpwait<1>(); }
        else                    { cpwait<0>(); }
        __syncthreads();

        const uint32_t sb = (uint32_t)st * STAGE_B;
#pragma unroll
        for (int kk = 0; kk < 2; kk++) {
            const uint32_t ko = sb + kk * 32;
            uint32_t a[2][4], b[8][2];
            ldm_x4(a[0], aoff + ko);
            ldm_x4(a[1], aoff + ko + 16 * SSTRIDE * 2);
#pragma unroll
            for (int ng = 0; ng < 4; ng++) {
                uint32_t r[4];
                ldm_x4(r, boff + ko + ng * 16 * SSTRIDE * 2);
                b[2 * ng][0] = r[0]; b[2 * ng][1] = r[2];
                b[2 * ng + 1][0] = r[1]; b[2 * ng + 1][1] = r[3];
            }
#pragma unroll
            for (int mt = 0; mt < 2; mt++)
#pragma unroll
                for (int nt = 0; nt < 8; nt++)
                    mma_h(acc[mt][nt], a[mt], b[nt][0], b[nt][1]);
        }
        __syncthreads();
    }
#undef PREF
}

// fused QKV: z selects weight + fp16 output
__global__ __launch_bounds__(256, 2)
void gemm_qkv(const __half* __restrict__ A,
              const __half* __restrict__ W0, const __half* __restrict__ W1,
              const __half* __restrict__ W2,
              __half* __restrict__ O0, __half* __restrict__ O1,
              __half* __restrict__ O2)
{
    extern __shared__ __half smemh[];
    const uint32_t smem = smem_u32(smemh);
    const int tid = threadIdx.x, lane = tid & 31, w = tid >> 5;
    const int m0 = blockIdx.y * 128, n0 = blockIdx.x * 128;
    const __half* Bm = (blockIdx.z == 0) ? W0 : (blockIdx.z == 1 ? W1 : W2);
    __half* C = (blockIdx.z == 0) ? O0 : (blockIdx.z == 1 ? O1 : O2);

    const int lr = tid & 127, lc = (tid >> 7) * 16;
    const __half* pA = A  + (size_t)(m0 + lr) * DIMN + lc;
    const __half* pB = Bm + (size_t)(n0 + lr) * DIMN + lc;
    const uint32_t dst0 = smem + (uint32_t)(lr * SSTRIDE + lc) * 2;

    const int wm = w & 3, wn = w >> 2;
    const uint32_t aoff = smem +
        (uint32_t)((wm * 32 + (lane & 15)) * SSTRIDE + (lane >> 4) * 8) * 2;
    const uint32_t boff = smem + TILE_B +
        (uint32_t)((wn * 64 + (lane & 15)) * SSTRIDE + (lane >> 4) * 8) * 2;

    float acc[2][8][4];
#pragma unroll
    for (int i = 0; i < 2; i++)
#pragma unroll
        for (int j = 0; j < 8; j++)
#pragma unroll
            for (int t = 0; t < 4; t++) acc[i][j][t] = 0.f;

    gemm_core(pA, pB, dst0, aoff, boff, acc);

    const int gr = lane >> 2, gc = (lane & 3) * 2;
#pragma unroll
    for (int mt = 0; mt < 2; mt++) {
        const int row = m0 + wm * 32 + mt * 16 + gr;
#pragma unroll
        for (int nt = 0; nt < 8; nt++) {
            const int col = n0 + wn * 64 + nt * 8 + gc;
            *(__half2*)(C + (size_t)row * DIMN + col) =
                __floats2half2_rn(acc[mt][nt][0], acc[mt][nt][1]);
            *(__half2*)(C + (size_t)(row + 8) * DIMN + col) =
                __floats2half2_rn(acc[mt][nt][2], acc[mt][nt][3]);
        }
    }
}

// final GEMM: fp32 out + bias
__global__ __launch_bounds__(256, 2)
void gemm_out(const __half* __restrict__ A, const __half* __restrict__ Bm,
              const float* __restrict__ bias, float* __restrict__ C)
{
    extern __shared__ __half smemh[];
    const uint32_t smem = smem_u32(smemh);
    const int tid = threadIdx.x, lane = tid & 31, w = tid >> 5;
    const int m0 = blockIdx.y * 128, n0 = blockIdx.x * 128;

    const int lr = tid & 127, lc = (tid >> 7) * 16;
    const __half* pA = A  + (size_t)(m0 + lr) * DIMN + lc;
    const __half* pB = Bm + (size_t)(n0 + lr) * DIMN + lc;
    const uint32_t dst0 = smem + (uint32_t)(lr * SSTRIDE + lc) * 2;

    const int wm = w & 3, wn = w >> 2;
    const uint32_t aoff = smem +
        (uint32_t)((wm * 32 + (lane & 15)) * SSTRIDE + (lane >> 4) * 8) * 2;
    const uint32_t boff = smem + TILE_B +
        (uint32_t)((wn * 64 + (lane & 15)) * SSTRIDE + (lane >> 4) * 8) * 2;

    float acc[2][8][4];
#pragma unroll
    for (int i = 0; i < 2; i++)
#pragma unroll
        for (int j = 0; j < 8; j++)
#pragma unroll
            for (int t = 0; t < 4; t++) acc[i][j][t] = 0.f;

    gemm_core(pA, pB, dst0, aoff, boff, acc);

    const int gr = lane >> 2, gc = (lane & 3) * 2;
#pragma unroll
    for (int mt = 0; mt < 2; mt++) {
        const int row = m0 + wm * 32 + mt * 16 + gr;
#pragma unroll
        for (int nt = 0; nt < 8; nt++) {
            const int col = n0 + wn * 64 + nt * 8 + gc;
            const float b0 = bias[col], b1 = bias[col + 1];
            *(float2*)(C + (size_t)row * DIMN + col) =
                make_float2(acc[mt][nt][0] + b0, acc[mt][nt][1] + b1);
            *(float2*)(C + (size_t)(row + 8) * DIMN + col) =
                make_float2(acc[mt][nt][2] + b0, acc[mt][nt][3] + b1);
        }
    }
}

// ---------------------------------------------------------------------------
// HMMA block-local attention + fused global attention.
// One CTA per (b, blk, head), 8 warps x 16 query rows (warp 7 takes tile 8).
// Warp 0 computes the 1x32 global-attention row from smem (gk/gv) and adds
// it to its own row-0 epilogue (warp-private: __syncwarp only).
// ---------------------------------------------------------------------------
#define AQS 72                               // smem row stride (halfs)
#define HQ  (144 * AQS)                      // halfs per tile
#define GK_OFF (3 * HQ)                      // 31104 halfs
#define GV_OFF (GK_OFF + 32 * AQS)           // +2304
#define GP_BYTE ((GV_OFF + 32 * AQS) * 2)    // bytes
#define GOUT_BYTE (GP_BYTE + 32 * 4)
#define AT_SMEM (GOUT_BYTE + 64 * 4)         // 71808 B

__global__ __launch_bounds__(256, 2)
void blk_attn_tc(const __half* __restrict__ q16, const __half* __restrict__ k16,
                 const __half* __restrict__ v16, __half* __restrict__ a16)
{
    extern __shared__ __half sh[];
    __half* Qs = sh;
    __half* Ks = sh + HQ;
    __half* Vs = sh + 2 * HQ;
    __half* gk = sh + GK_OFF;
    __half* gv = sh + GV_OFF;
    float* gp   = (float*)((char*)sh + GP_BYTE);
    float* gout = (float*)((char*)sh + GOUT_BYTE);

    const int bid = blockIdx.x;
    const int h = bid & 15, blk = (bid >> 4) & 31, b = bid >> 9;
    const size_t gbase = ((size_t)(b * NLEN + blk * BLKLEN)) * DIMN + h * DK;
    const int tid = threadIdx.x, lane = tid & 31, wid = tid >> 5;

    // zero pad rows 129..143 (15 rows x 8 chunks x 3 tensors)
    const uint4 z4 = make_uint4(0, 0, 0, 0);
    for (int i = tid; i < 360; i += 256) {
        const int t = i / 120, j = i % 120;
        const int r = 129 + (j >> 3), c = (j & 7) * 8;
        __half* base = (t == 0) ? Qs : (t == 1) ? Ks : Vs;
        *(uint4*)&base[r * AQS + c] = z4;
    }
    // main tiles rows 0..128 (129 rows x 8 chunks)
    for (int i = tid; i < 1032; i += 256) {
        const int r = i >> 3, c = (i & 7) * 8;
        const uint32_t so = (uint32_t)(r * AQS + c) * 2;
        const size_t g = gbase + (size_t)r * DIMN + c;
        cp16(smem_u32(Qs) + so, q16 + g);
        cp16(smem_u32(Ks) + so, k16 + g);
        cp16(smem_u32(Vs) + so, v16 + g);
    }
    // global K/V: first tokens of the 32 blocks (32 rows x 8 chunks); 1 iter
    {
        const int r = tid >> 3, c = (tid & 7) * 8;
        const size_t g = ((size_t)(b * NLEN + r * BLKLEN)) * DIMN + h * DK + c;
        const uint32_t so = (uint32_t)(r * AQS + c) * 2;
        cp16(smem_u32(gk) + so, k16 + g);
        cp16(smem_u32(gv) + so, v16 + g);
    }
    cp_commit();
    cpwait<0>();
    __syncthreads();

    const float scale = 0.125f;

    // ---- warp 0: global attention for this block's first token ----
    if (wid == 0) {
        float s = 0.f;
#pragma unroll
        for (int i = 0; i < DK / 2; i++) {
            float2 qf = __half22float2(*(const __half2*)&Qs[2 * i]);
            float2 kf = __half22float2(*(const __half2*)&gk[lane * AQS + 2 * i]);
            s += qf.x * kf.x + qf.y * kf.y;
        }
        float p = __expf(s * scale);
        float lsum = p;
#pragma unroll
        for (int d = 1; d < 32; d <<= 1)
            lsum += __shfl_xor_sync(0xFFFFFFFFu, lsum, d);
        gp[lane] = p;
        __syncwarp();
        const float inv = 1.0f / lsum;
        float o0 = 0.f, o1 = 0.f;
#pragma unroll
        for (int k = 0; k < NB; k++) {
            const float pk = gp[k];
            float2 vf = __half22float2(*(const __half2*)&gv[k * AQS + 2 * lane]);
            o0 += pk * vf.x; o1 += pk * vf.y;
        }
        gout[2 * lane]     = o0 * inv;
        gout[2 * lane + 1] = o1 * inv;
        __syncwarp();
    }

    const int cbase = (lane & 3) * 2;
    const int gr = lane >> 2;
    const uint32_t loff = (uint32_t)((lane & 15) * AQS + (lane >> 4) * 8) * 2;
    const int vmat = lane >> 3;
    const uint32_t vb = smem_u32(Vs) +
        (uint32_t)(((vmat & 1) * 8 + (lane & 7)) * AQS + (vmat >> 1) * 8) * 2;

    const int niter = (wid == 7) ? 2 : 1;
    for (int it = 0; it < niter; it++) {
        const int t = (it == 0) ? wid : 8;
        const int m0 = t * 16;

        // Q fragments (4 k-steps of DK=64)
        uint32_t aq[4][4];
        {
            const uint32_t qb = smem_u32(Qs) + (uint32_t)(m0 * AQS) * 2 + loff;
#pragma unroll
            for (int ks = 0; ks < 4; ks++) ldm_x4(aq[ks], qb + ks * 32);
        }

        // S = QK^T, exp, pack to fp16 P on the fly
        uint32_t P2[17][2];
        float l0 = 0.f, l1 = 0.f;
        const uint32_t kb = smem_u32(Ks) + loff;
#pragma unroll
        for (int jp = 0; jp < 8; jp++) {
            float e0[4] = {0.f, 0.f, 0.f, 0.f};
            float e1[4] = {0.f, 0.f, 0.f, 0.f};
            const uint32_t kjb = kb + (uint32_t)(jp * 16 * AQS) * 2;
#pragma unroll
            for (int ks = 0; ks < 4; ks++) {
                uint32_t r[4];
                ldm_x4(r, kjb + ks * 32);
                mma_h(e0, aq[ks], r[0], r[2]);
                mma_h(e1, aq[ks], r[1], r[3]);
            }
            float p00 = __expf(e0[0] * scale), p01 = __expf(e0[1] * scale);
            float p02 = __expf(e0[2] * scale), p03 = __expf(e0[3] * scale);
            float p10 = __expf(e1[0] * scale), p11 = __expf(e1[1] * scale);
            float p12 = __expf(e1[2] * scale), p13 = __expf(e1[3] * scale);
            l0 += (p00 + p01) + (p10 + p11);
            l1 += (p02 + p03) + (p12 + p13);
            P2[2 * jp][0] = packh2(p00, p01);
            P2[2 * jp][1] = packh2(p02, p03);
            P2[2 * jp + 1][0] = packh2(p10, p11);
            P2[2 * jp + 1][1] = packh2(p12, p13);
        }
        {   // key tile 16: keys 128..135, only key 128 valid
            float e0[4] = {0.f, 0.f, 0.f, 0.f};
            const uint32_t kjb = kb + (uint32_t)(128 * AQS) * 2;
#pragma unroll
            for (int ks = 0; ks < 4; ks++) {
                uint32_t r[4];
                ldm_x4(r, kjb + ks * 32);
                mma_h(e0, aq[ks], r[0], r[2]);
            }
            const bool v = (cbase == 0);
            float p0 = v ? __expf(e0[0] * scale) : 0.f;
            float p2 = v ? __expf(e0[2] * scale) : 0.f;
            l0 += p0; l1 += p2;
            P2[16][0] = packh2(p0, 0.f);
            P2[16][1] = packh2(p2, 0.f);
        }
        l0 += __shfl_xor_sync(0xFFFFFFFFu, l0, 1);
        l0 += __shfl_xor_sync(0xFFFFFFFFu, l0, 2);
        l1 += __shfl_xor_sync(0xFFFFFFFFu, l1, 1);
        l1 += __shfl_xor_sync(0xFFFFFFFFu, l1, 2);

        // O = P V
        float oacc[8][4];
#pragma unroll
        for (int g = 0; g < 8; g++)
#pragma unroll
            for (int u = 0; u < 4; u++) oacc[g][u] = 0.f;

#pragma unroll
        for (int kp = 0; kp < 9; kp++) {
            uint32_t pa[4];
            pa[0] = P2[2 * kp][0];
            pa[1] = P2[2 * kp][1];
            if (kp < 8) { pa[2] = P2[2 * kp + 1][0]; pa[3] = P2[2 * kp + 1][1]; }
            else        { pa[2] = 0u; pa[3] = 0u; }
            const uint32_t vkb = vb + (uint32_t)(kp * 16 * AQS) * 2;
#pragma unroll
            for (int g = 0; g < 4; g++) {
                uint32_t r[4];
                ldm_x4_t(r, vkb + g * 32);
                mma_h(oacc[2 * g],     pa, r[0], r[1]);
                mma_h(oacc[2 * g + 1], pa, r[2], r[3]);
            }
        }

        // epilogue
        const float rl0 = 1.0f / l0, rl1 = 1.0f / l1;
        const int r0 = m0 + gr, r1 = r0 + 8;
#pragma unroll
        for (int g = 0; g < 8; g++) {
            const int col = g * 8 + cbase;
            float o0 = oacc[g][0] * rl0, o1 = oacc[g][1] * rl0;
            float o2 = oacc[g][2] * rl1, o3 = oacc[g][3] * rl1;
            if (r0 == 0) { o0 += gout[col]; o1 += gout[col + 1]; }
            if (r0 < BLKLEN)
                *(__half2*)(a16 + gbase + (size_t)r0 * DIMN + col) =
                    __floats2half2_rn(o0, o1);
            if (r1 < BLKLEN)
                *(__half2*)(a16 + gbase + (size_t)r1 * DIMN + col) =
                    __floats2half2_rn(o2, o3);
        }
    }
}

// ---------------------------------------------------------------------------
extern "C" void kernel_launch(void* const* d_in, const int* in_sizes, int n_in,
                              void* d_out, int out_size)
{
    const float* x  = (const float*)d_in[0];
    const float* Wq = (const float*)d_in[1];
    const float* Wk = (const float*)d_in[2];
    const float* Wv = (const float*)d_in[3];
    const float* Wo = (const float*)d_in[4];
    const float* bo = (const float*)d_in[5];
    float* out = (float*)d_out;

    __half *x16, *q16, *k16, *v16, *a16, *w16;
    cudaGetSymbolAddress((void**)&x16, g_x16);
    cudaGetSymbolAddress((void**)&q16, g_q16);
    cudaGetSymbolAddress((void**)&k16, g_k16);
    cudaGetSymbolAddress((void**)&v16, g_v16);
    cudaGetSymbolAddress((void**)&a16, g_a16);
    cudaGetSymbolAddress((void**)&w16, g_w16);

    cudaFuncSetAttribute(gemm_qkv, cudaFuncAttributeMaxDynamicSharedMemorySize, GEMM_SMEM);
    cudaFuncSetAttribute(gemm_out, cudaFuncAttributeMaxDynamicSharedMemorySize, GEMM_SMEM);
    cudaFuncSetAttribute(blk_attn_tc, cudaFuncAttributeMaxDynamicSharedMemorySize, AT_SMEM);

    const int W = DIMN * DIMN;
    const int n4x = TOK * DIMN / 4;
    const int n4w = W / 4;

    cvt_h4<<<(n4x + 255) / 256, 256>>>((const float4*)x, (__half2*)x16, n4x);
    dim3 gW((n4w + 255) / 256, 4);
    cvt_w4<<<gW, 256>>>((const float4*)Wq, (const float4*)Wk,
                        (const float4*)Wv, (const float4*)Wo,
                        (__half2*)w16, n4w);

    dim3 gQKV(DIMN / 128, TOK / 128, 3);   // (8, 129, 3)
    gemm_qkv<<<gQKV, 256, GEMM_SMEM>>>(x16,
        w16 + 0 * W, w16 + 1 * W, w16 + 2 * W, q16, k16, v16);

    blk_attn_tc<<<B_SZ * NB * HEADS, 256, AT_SMEM>>>(q16, k16, v16, a16);

    dim3 gO(DIMN / 128, TOK / 128);        // (8, 129)
    gemm_out<<<gO, 256, GEMM_SMEM>>>(a16, w16 + 3 * W, bo, out);
}